// round 1
// baseline (speedup 1.0000x reference)
#include <cuda_runtime.h>
#include <math.h>

#define B_ 8
#define N_ 2048
#define D_ 256
#define K_ 512
#define R_ 32

// Output packing: scores1 [B,N,N] | soi [B,K*R,3] | rel_e [B,K*R,D], all float32
static constexpr size_t SCORES_ELEMS = (size_t)B_ * N_ * N_;
static constexpr size_t SOI_OFF      = SCORES_ELEMS;
static constexpr size_t RELE_OFF     = SOI_OFF + (size_t)B_ * K_ * R_ * 3;

// Scratch (__device__ globals; no allocation allowed)
__device__ float g_diag[B_ * N_];
__device__ int   g_inst[B_ * K_];

// ---------------------------------------------------------------------------
// Kernel 1: batched GEMM  S[b,i,j] = sum_d q[b,i,d] * k[b,j,d]
// 128x128 tile, BK=8, 256 threads, 8x8 microtile per thread.
// ---------------------------------------------------------------------------
#define TBM 128
#define TBN 128
#define TBK 8

__global__ __launch_bounds__(256) void gemm_qkT_kernel(
    const float* __restrict__ Q, const float* __restrict__ Km, float* __restrict__ S)
{
    __shared__ float As[TBK][TBM];
    __shared__ float Bs[TBK][TBN];

    const int b  = blockIdx.z;
    const int m0 = blockIdx.y * TBM;
    const int n0 = blockIdx.x * TBN;
    const float* qb = Q  + (size_t)b * N_ * D_;
    const float* kb = Km + (size_t)b * N_ * D_;

    const int tid = threadIdx.x;
    const int tx = tid & 15;   // 0..15  -> 8 cols each
    const int ty = tid >> 4;   // 0..15  -> 8 rows each

    // loader mapping: 256 threads load 128x8 tile as float4
    const int lr = tid >> 1;          // 0..127
    const int lc = (tid & 1) << 2;    // 0 or 4

    const float* qptr = qb + (size_t)(m0 + lr) * D_ + lc;
    const float* kptr = kb + (size_t)(n0 + lr) * D_ + lc;

    float acc[8][8];
#pragma unroll
    for (int i = 0; i < 8; i++)
#pragma unroll
        for (int j = 0; j < 8; j++) acc[i][j] = 0.0f;

    for (int k0 = 0; k0 < D_; k0 += TBK) {
        float4 av = *(const float4*)(qptr + k0);
        float4 bv = *(const float4*)(kptr + k0);
        As[lc + 0][lr] = av.x; As[lc + 1][lr] = av.y;
        As[lc + 2][lr] = av.z; As[lc + 3][lr] = av.w;
        Bs[lc + 0][lr] = bv.x; Bs[lc + 1][lr] = bv.y;
        Bs[lc + 2][lr] = bv.z; Bs[lc + 3][lr] = bv.w;
        __syncthreads();

#pragma unroll
        for (int kk = 0; kk < TBK; kk++) {
            float a[8], bb[8];
#pragma unroll
            for (int i = 0; i < 8; i++) a[i] = As[kk][ty * 8 + i];
#pragma unroll
            for (int j = 0; j < 8; j++) bb[j] = Bs[kk][tx * 8 + j];
#pragma unroll
            for (int i = 0; i < 8; i++)
#pragma unroll
                for (int j = 0; j < 8; j++)
                    acc[i][j] = fmaf(a[i], bb[j], acc[i][j]);
        }
        __syncthreads();
    }

#pragma unroll
    for (int i = 0; i < 8; i++) {
        float4* p = (float4*)(S + ((size_t)b * N_ + m0 + ty * 8 + i) * N_ + n0 + tx * 8);
        p[0] = make_float4(acc[i][0], acc[i][1], acc[i][2], acc[i][3]);
        p[1] = make_float4(acc[i][4], acc[i][5], acc[i][6], acc[i][7]);
    }
}

// ---------------------------------------------------------------------------
// Kernel 2: per-row softmax stats -> diagonal softmax prob
// one block (256 threads) per row; 2048 elements per row.
// ---------------------------------------------------------------------------
__global__ __launch_bounds__(256) void rowstats_kernel(const float* __restrict__ S)
{
    const int row = blockIdx.x;            // 0 .. B*N-1
    const int i   = row & (N_ - 1);
    const float* r = S + (size_t)row * N_;
    const int tid = threadIdx.x;

    float vals[8];
    float lm = -INFINITY;
#pragma unroll
    for (int t = 0; t < 8; t++) {
        vals[t] = r[t * 256 + tid];
        lm = fmaxf(lm, vals[t]);
    }

    __shared__ float red[8];
    // block max
#pragma unroll
    for (int o = 16; o > 0; o >>= 1) lm = fmaxf(lm, __shfl_xor_sync(0xffffffffu, lm, o));
    if ((tid & 31) == 0) red[tid >> 5] = lm;
    __syncthreads();
    float m = red[0];
#pragma unroll
    for (int w = 1; w < 8; w++) m = fmaxf(m, red[w]);
    __syncthreads();

    float ls = 0.0f;
#pragma unroll
    for (int t = 0; t < 8; t++) ls += expf(vals[t] - m);
#pragma unroll
    for (int o = 16; o > 0; o >>= 1) ls += __shfl_xor_sync(0xffffffffu, ls, o);
    if ((tid & 31) == 0) red[tid >> 5] = ls;
    __syncthreads();

    if (tid == 0) {
        float Z = 0.0f;
#pragma unroll
        for (int w = 0; w < 8; w++) Z += red[w];
        g_diag[row] = expf(r[i] - m) / Z;
    }
}

// ---------------------------------------------------------------------------
// Kernel 3: per-batch top-512 of diag (desc value, asc index tiebreak),
// then sort selected indices ascending. One block of 1024 threads per batch.
// ---------------------------------------------------------------------------
__global__ __launch_bounds__(1024) void topk_inst_kernel()
{
    __shared__ float v[N_];
    __shared__ int   id[N_];
    __shared__ int   sel[K_];

    const int b   = blockIdx.x;
    const int tid = threadIdx.x;

    for (int i = tid; i < N_; i += 1024) { v[i] = g_diag[b * N_ + i]; id[i] = i; }
    __syncthreads();

    // bitonic full sort: descending by value, ascending index on ties
    for (int k = 2; k <= N_; k <<= 1) {
        for (int j = k >> 1; j > 0; j >>= 1) {
            for (int i = tid; i < N_; i += 1024) {
                int ixj = i ^ j;
                if (ixj > i) {
                    float vi = v[i], vx = v[ixj];
                    int ii = id[i], ix = id[ixj];
                    bool beforeXI = (vx > vi) || (vx == vi && ix < ii);
                    bool dir = ((i & k) == 0);
                    if (beforeXI == dir) {
                        v[i] = vx; v[ixj] = vi; id[i] = ix; id[ixj] = ii;
                    }
                }
            }
            __syncthreads();
        }
    }

    if (tid < K_) sel[tid] = id[tid];
    __syncthreads();

    // sort selected indices ascending
    for (int k = 2; k <= K_; k <<= 1) {
        for (int j = k >> 1; j > 0; j >>= 1) {
            for (int i = tid; i < K_; i += 1024) {
                int ixj = i ^ j;
                if (ixj > i) {
                    int a = sel[i], c = sel[ixj];
                    bool beforeXI = (c < a);
                    bool dir = ((i & k) == 0);
                    if (beforeXI == dir) { sel[i] = c; sel[ixj] = a; }
                }
            }
            __syncthreads();
        }
    }

    if (tid < K_) g_inst[b * K_ + tid] = sel[tid];
}

// ---------------------------------------------------------------------------
// Kernel 4: per (b, a): gather scores at instance columns, top-32
// (softmax monotone per row -> rank by raw score; diag forced +inf),
// emit soi and layernormed rel_e. One block of 256 threads per row.
// ---------------------------------------------------------------------------
__global__ __launch_bounds__(256) void rel_kernel(
    const float* __restrict__ S, const float* __restrict__ Q, float* __restrict__ out)
{
    const int blk = blockIdx.x;
    const int b = blk >> 9;        // / 512
    const int a = blk & (K_ - 1);
    const int tid = threadIdx.x;

    __shared__ int   s_inst[K_];
    __shared__ float v[K_];
    __shared__ int   id[K_];
    __shared__ int   cols[R_];
    __shared__ float red[8];

    for (int c = tid; c < K_; c += 256) s_inst[c] = g_inst[b * K_ + c];
    __syncthreads();

    const int ia = s_inst[a];
    const float* Srow = S + ((size_t)b * N_ + ia) * N_;
    for (int c = tid; c < K_; c += 256) {
        float x = Srow[s_inst[c]];
        if (c == a) x = __int_as_float(0x7f800000);  // +inf: forced diagonal
        v[c] = x; id[c] = c;
    }
    __syncthreads();

    // bitonic sort 512 desc by value, asc index on ties
    for (int k = 2; k <= K_; k <<= 1) {
        for (int j = k >> 1; j > 0; j >>= 1) {
            for (int i = tid; i < K_; i += 256) {
                int ixj = i ^ j;
                if (ixj > i) {
                    float vi = v[i], vx = v[ixj];
                    int ii = id[i], ix = id[ixj];
                    bool beforeXI = (vx > vi) || (vx == vi && ix < ii);
                    bool dir = ((i & k) == 0);
                    if (beforeXI == dir) {
                        v[i] = vx; v[ixj] = vi; id[i] = ix; id[ixj] = ii;
                    }
                }
            }
            __syncthreads();
        }
    }

    if (tid == 0) {
        // insertion-sort top-32 column indices ascending
        for (int r = 0; r < R_; r++) {
            int x = id[r];
            int p = r;
            while (p > 0 && cols[p - 1] > x) { cols[p] = cols[p - 1]; p--; }
            cols[p] = x;
        }
    }
    __syncthreads();

    const float qa = Q[((size_t)b * N_ + ia) * D_ + tid];
    float* soi = out + SOI_OFF  + (size_t)(b * K_ + a) * R_ * 3;
    float* re  = out + RELE_OFF + (size_t)(b * K_ + a) * R_ * D_;

    for (int r = 0; r < R_; r++) {
        const int obj = s_inst[cols[r]];
        if (tid == 0) {
            soi[r * 3 + 0] = (float)b;
            soi[r * 3 + 1] = (float)ia;
            soi[r * 3 + 2] = (float)obj;
        }
        float x = qa + Q[((size_t)b * N_ + obj) * D_ + tid];

        // mean
        float s = x;
#pragma unroll
        for (int o = 16; o > 0; o >>= 1) s += __shfl_xor_sync(0xffffffffu, s, o);
        if ((tid & 31) == 0) red[tid >> 5] = s;
        __syncthreads();
        float mu = 0.0f;
#pragma unroll
        for (int w = 0; w < 8; w++) mu += red[w];
        mu *= (1.0f / 256.0f);
        __syncthreads();

        // variance (biased, two-pass)
        float d = x - mu;
        float s2 = d * d;
#pragma unroll
        for (int o = 16; o > 0; o >>= 1) s2 += __shfl_xor_sync(0xffffffffu, s2, o);
        if ((tid & 31) == 0) red[tid >> 5] = s2;
        __syncthreads();
        float var = 0.0f;
#pragma unroll
        for (int w = 0; w < 8; w++) var += red[w];
        var *= (1.0f / 256.0f);

        re[r * D_ + tid] = d * rsqrtf(var + 1e-5f);
        __syncthreads();
    }
}

// ---------------------------------------------------------------------------
extern "C" void kernel_launch(void* const* d_in, const int* in_sizes, int n_in,
                              void* d_out, int out_size)
{
    const float* q = (const float*)d_in[0];
    const float* k = (const float*)d_in[1];
    float* out = (float*)d_out;
    float* S = out;  // scores1 region at offset 0

    dim3 gGemm(N_ / TBN, N_ / TBM, B_);
    gemm_qkT_kernel<<<gGemm, 256>>>(q, k, S);

    rowstats_kernel<<<B_ * N_, 256>>>(S);

    topk_inst_kernel<<<B_, 1024>>>();

    rel_kernel<<<B_ * K_, 256>>>(S, q, out);
}

// round 2
// speedup vs baseline: 1.3409x; 1.3409x over previous
#include <cuda_runtime.h>
#include <math.h>

#define B_ 8
#define N_ 2048
#define D_ 256
#define K_ 512
#define R_ 32
#define NTILES 16   // N_ / 128 column tiles

// Output packing: scores1 [B,N,N] | soi [B,K*R,3] | rel_e [B,K*R,D], all float32
static constexpr size_t SCORES_ELEMS = (size_t)B_ * N_ * N_;
static constexpr size_t SOI_OFF      = SCORES_ELEMS;
static constexpr size_t RELE_OFF     = SOI_OFF + (size_t)B_ * K_ * R_ * 3;

// Scratch (__device__ globals; no allocation allowed)
__device__ float2 g_part[B_ * N_ * NTILES];  // per (row, coltile): (max, sumexp)
__device__ float  g_diag[B_ * N_];
__device__ int    g_inst[B_ * K_];
__device__ int    g_obj [B_ * K_ * R_];

// ---------------------------------------------------------------------------
// Kernel 1: batched GEMM  S[b,i,j] = sum_d q[b,i,d] * k[b,j,d]
// 128x128 tile, BK=8, 256 threads, 8x8 microtile. Epilogue computes per-row
// softmax partials (max, sum exp) for the 128-col tile -> g_part.
// ---------------------------------------------------------------------------
#define TBM 128
#define TBN 128
#define TBK 8

__global__ __launch_bounds__(256) void gemm_qkT_kernel(
    const float* __restrict__ Q, const float* __restrict__ Km, float* __restrict__ S)
{
    __shared__ float As[TBK][TBM];
    __shared__ float Bs[TBK][TBN];

    const int b  = blockIdx.z;
    const int m0 = blockIdx.y * TBM;
    const int n0 = blockIdx.x * TBN;
    const float* qb = Q  + (size_t)b * N_ * D_;
    const float* kb = Km + (size_t)b * N_ * D_;

    const int tid = threadIdx.x;
    const int tx = tid & 15;   // 0..15  -> 8 cols each
    const int ty = tid >> 4;   // 0..15  -> 8 rows each

    const int lr = tid >> 1;          // 0..127
    const int lc = (tid & 1) << 2;    // 0 or 4

    const float* qptr = qb + (size_t)(m0 + lr) * D_ + lc;
    const float* kptr = kb + (size_t)(n0 + lr) * D_ + lc;

    float acc[8][8];
#pragma unroll
    for (int i = 0; i < 8; i++)
#pragma unroll
        for (int j = 0; j < 8; j++) acc[i][j] = 0.0f;

    for (int k0 = 0; k0 < D_; k0 += TBK) {
        float4 av = *(const float4*)(qptr + k0);
        float4 bv = *(const float4*)(kptr + k0);
        As[lc + 0][lr] = av.x; As[lc + 1][lr] = av.y;
        As[lc + 2][lr] = av.z; As[lc + 3][lr] = av.w;
        Bs[lc + 0][lr] = bv.x; Bs[lc + 1][lr] = bv.y;
        Bs[lc + 2][lr] = bv.z; Bs[lc + 3][lr] = bv.w;
        __syncthreads();

#pragma unroll
        for (int kk = 0; kk < TBK; kk++) {
            float a[8], bb[8];
#pragma unroll
            for (int i = 0; i < 8; i++) a[i] = As[kk][ty * 8 + i];
#pragma unroll
            for (int j = 0; j < 8; j++) bb[j] = Bs[kk][tx * 8 + j];
#pragma unroll
            for (int i = 0; i < 8; i++)
#pragma unroll
                for (int j = 0; j < 8; j++)
                    acc[i][j] = fmaf(a[i], bb[j], acc[i][j]);
        }
        __syncthreads();
    }

    // store scores
#pragma unroll
    for (int i = 0; i < 8; i++) {
        float4* p = (float4*)(S + ((size_t)b * N_ + m0 + ty * 8 + i) * N_ + n0 + tx * 8);
        p[0] = make_float4(acc[i][0], acc[i][1], acc[i][2], acc[i][3]);
        p[1] = make_float4(acc[i][4], acc[i][5], acc[i][6], acc[i][7]);
    }

    // epilogue: per-row (max, sum exp) over this 128-col tile.
    // threads with same ty are an aligned 16-lane group in the warp.
    const int tile_n = blockIdx.x;
#pragma unroll
    for (int i = 0; i < 8; i++) {
        float rm = acc[i][0];
#pragma unroll
        for (int j = 1; j < 8; j++) rm = fmaxf(rm, acc[i][j]);
#pragma unroll
        for (int o = 8; o > 0; o >>= 1)
            rm = fmaxf(rm, __shfl_xor_sync(0xffffffffu, rm, o));
        float rs = 0.0f;
#pragma unroll
        for (int j = 0; j < 8; j++) rs += expf(acc[i][j] - rm);
#pragma unroll
        for (int o = 8; o > 0; o >>= 1)
            rs += __shfl_xor_sync(0xffffffffu, rs, o);
        if (tx == 0)
            g_part[((size_t)b * N_ + m0 + ty * 8 + i) * NTILES + tile_n] =
                make_float2(rm, rs);
    }
}

// ---------------------------------------------------------------------------
// Kernel 2: combine per-tile partials -> diagonal softmax prob per row
// ---------------------------------------------------------------------------
__global__ __launch_bounds__(128) void combine_kernel(const float* __restrict__ S)
{
    const int row = blockIdx.x * 128 + threadIdx.x;   // 0 .. B*N-1
    const float2* p = g_part + (size_t)row * NTILES;
    float2 pv[NTILES];
    float m = -INFINITY;
#pragma unroll
    for (int t = 0; t < NTILES; t++) { pv[t] = p[t]; m = fmaxf(m, pv[t].x); }
    float Z = 0.0f;
#pragma unroll
    for (int t = 0; t < NTILES; t++) Z += pv[t].y * expf(pv[t].x - m);
    const int i = row & (N_ - 1);
    g_diag[row] = expf(S[(size_t)row * N_ + i] - m) / Z;
}

// ---------------------------------------------------------------------------
// Kernel 3: per-batch top-512 of diag (desc value, asc index tiebreak),
// then sort selected indices ascending. One block of 1024 threads per batch.
// ---------------------------------------------------------------------------
__global__ __launch_bounds__(1024) void topk_inst_kernel()
{
    __shared__ float v[N_];
    __shared__ int   id[N_];
    __shared__ int   sel[K_];

    const int b   = blockIdx.x;
    const int tid = threadIdx.x;

    for (int i = tid; i < N_; i += 1024) { v[i] = g_diag[b * N_ + i]; id[i] = i; }
    __syncthreads();

    for (int k = 2; k <= N_; k <<= 1) {
        for (int j = k >> 1; j > 0; j >>= 1) {
            for (int i = tid; i < N_; i += 1024) {
                int ixj = i ^ j;
                if (ixj > i) {
                    float vi = v[i], vx = v[ixj];
                    int ii = id[i], ix = id[ixj];
                    bool beforeXI = (vx > vi) || (vx == vi && ix < ii);
                    bool dir = ((i & k) == 0);
                    if (beforeXI == dir) {
                        v[i] = vx; v[ixj] = vi; id[i] = ix; id[ixj] = ii;
                    }
                }
            }
            __syncthreads();
        }
    }

    if (tid < K_) sel[tid] = id[tid];
    __syncthreads();

    for (int k = 2; k <= K_; k <<= 1) {
        for (int j = k >> 1; j > 0; j >>= 1) {
            for (int i = tid; i < K_; i += 1024) {
                int ixj = i ^ j;
                if (ixj > i) {
                    int a = sel[i], c = sel[ixj];
                    bool beforeXI = (c < a);
                    bool dir = ((i & k) == 0);
                    if (beforeXI == dir) { sel[i] = c; sel[ixj] = a; }
                }
            }
            __syncthreads();
        }
    }

    if (tid < K_) g_inst[b * K_ + tid] = sel[tid];
}

// ---------------------------------------------------------------------------
// Kernel 4: warp-level top-32 selection. One warp per (b,a). All in registers
// via shfl: bitonic-sort each 32-chunk desc, merge-and-keep-top-32 across
// the 16 chunks, then sort the 32 winning column positions ascending.
// Writes soi and g_obj.
// ---------------------------------------------------------------------------
__device__ __forceinline__ bool kv_before(float va, int ia, float vb, int ib) {
    return (va > vb) || (va == vb && ia < ib);
}

__global__ __launch_bounds__(256) void select_kernel(
    const float* __restrict__ S, float* __restrict__ out)
{
    const int warp = threadIdx.x >> 5;
    const int lane = threadIdx.x & 31;
    const int b = blockIdx.x >> 6;                 // 64 blocks per batch
    const int a = ((blockIdx.x & 63) << 3) + warp; // 8 warps -> 8 rows

    __shared__ int s_inst[K_];
    for (int c = threadIdx.x; c < K_; c += 256) s_inst[c] = g_inst[b * K_ + c];
    __syncthreads();

    const int ia = s_inst[a];
    const float* Srow = S + ((size_t)b * N_ + ia) * N_;

    float v; int idx;   // running top-32 (descending by value, asc index ties)

    // ---- chunk 0: load + full bitonic sort (descending) ----
    {
        int c = lane;
        float x = Srow[s_inst[c]];
        if (c == a) x = __int_as_float(0x7f800000);   // +inf diagonal
        v = x; idx = c;
#pragma unroll
        for (int k = 2; k <= 32; k <<= 1) {
#pragma unroll
            for (int j = k >> 1; j > 0; j >>= 1) {
                float pv = __shfl_xor_sync(0xffffffffu, v, j);
                int   pi = __shfl_xor_sync(0xffffffffu, idx, j);
                bool desc  = ((lane & k) == 0);
                bool lower = ((lane & j) == 0);
                bool win = kv_before(v, idx, pv, pi);
                bool take = (desc == lower) ? !win : win;
                if (take) { v = pv; idx = pi; }
            }
        }
    }

    // ---- chunks 1..15: sort chunk desc, merge keep-top-32, clean ----
    for (int t = 1; t < 16; t++) {
        int c = t * 32 + lane;
        float v2 = Srow[s_inst[c]];
        if (c == a) v2 = __int_as_float(0x7f800000);
        int i2 = c;
#pragma unroll
        for (int k = 2; k <= 32; k <<= 1) {
#pragma unroll
            for (int j = k >> 1; j > 0; j >>= 1) {
                float pv = __shfl_xor_sync(0xffffffffu, v2, j);
                int   pi = __shfl_xor_sync(0xffffffffu, i2, j);
                bool desc  = ((lane & k) == 0);
                bool lower = ((lane & j) == 0);
                bool win = kv_before(v2, i2, pv, pi);
                bool take = (desc == lower) ? !win : win;
                if (take) { v2 = pv; i2 = pi; }
            }
        }
        // elementwise winner of L[l] vs C[31-l]  (lane^31 = 31-lane)
        float cv = __shfl_xor_sync(0xffffffffu, v2, 31);
        int   ci = __shfl_xor_sync(0xffffffffu, i2, 31);
        if (!kv_before(v, idx, cv, ci)) { v = cv; idx = ci; }
        // bitonic clean (descending)
#pragma unroll
        for (int j = 16; j > 0; j >>= 1) {
            float pv = __shfl_xor_sync(0xffffffffu, v, j);
            int   pi = __shfl_xor_sync(0xffffffffu, idx, j);
            bool lower = ((lane & j) == 0);
            bool win = kv_before(v, idx, pv, pi);
            bool take = lower ? !win : win;
            if (take) { v = pv; idx = pi; }
        }
    }

    // ---- sort the 32 winning column positions ascending ----
#pragma unroll
    for (int k = 2; k <= 32; k <<= 1) {
#pragma unroll
        for (int j = k >> 1; j > 0; j >>= 1) {
            int pi = __shfl_xor_sync(0xffffffffu, idx, j);
            bool asc   = ((lane & k) == 0);
            bool lower = ((lane & j) == 0);
            bool win = (idx < pi);
            bool take = (asc == lower) ? !win : win;
            if (take) idx = pi;
        }
    }

    const int obj = s_inst[idx];
    const size_t base = (size_t)b * K_ + a;
    g_obj[base * R_ + lane] = obj;
    float* soi = out + SOI_OFF + base * R_ * 3 + lane * 3;
    soi[0] = (float)b;
    soi[1] = (float)ia;
    soi[2] = (float)obj;
}

// ---------------------------------------------------------------------------
// Kernel 5: emit rel_e. One warp per relation; each lane owns 8 floats of D.
// ---------------------------------------------------------------------------
__global__ __launch_bounds__(256) void emit_kernel(
    const float* __restrict__ Q, float* __restrict__ out)
{
    const int rel  = blockIdx.x * 8 + (threadIdx.x >> 5);
    const int lane = threadIdx.x & 31;
    const int b   = rel >> 14;                 // / (K_*R_)
    const int rem = rel & 16383;
    const int a   = rem >> 5;                  // / R_
    const int ia  = g_inst[b * K_ + a];
    const int obj = g_obj[rel];

    const float4* qa = (const float4*)(Q + ((size_t)b * N_ + ia)  * D_) + lane * 2;
    const float4* qo = (const float4*)(Q + ((size_t)b * N_ + obj) * D_) + lane * 2;
    float4 x0 = qa[0], x1 = qa[1];
    float4 y0 = qo[0], y1 = qo[1];
    x0.x += y0.x; x0.y += y0.y; x0.z += y0.z; x0.w += y0.w;
    x1.x += y1.x; x1.y += y1.y; x1.z += y1.z; x1.w += y1.w;

    float s = x0.x + x0.y + x0.z + x0.w + x1.x + x1.y + x1.z + x1.w;
#pragma unroll
    for (int o = 16; o > 0; o >>= 1) s += __shfl_xor_sync(0xffffffffu, s, o);
    const float mu = s * (1.0f / 256.0f);

    float d0x = x0.x - mu, d0y = x0.y - mu, d0z = x0.z - mu, d0w = x0.w - mu;
    float d1x = x1.x - mu, d1y = x1.y - mu, d1z = x1.z - mu, d1w = x1.w - mu;
    float s2 = d0x*d0x + d0y*d0y + d0z*d0z + d0w*d0w
             + d1x*d1x + d1y*d1y + d1z*d1z + d1w*d1w;
#pragma unroll
    for (int o = 16; o > 0; o >>= 1) s2 += __shfl_xor_sync(0xffffffffu, s2, o);
    const float r = rsqrtf(s2 * (1.0f / 256.0f) + 1e-5f);

    float4* o4 = (float4*)(out + RELE_OFF + (size_t)rel * D_) + lane * 2;
    o4[0] = make_float4(d0x * r, d0y * r, d0z * r, d0w * r);
    o4[1] = make_float4(d1x * r, d1y * r, d1z * r, d1w * r);
}

// ---------------------------------------------------------------------------
extern "C" void kernel_launch(void* const* d_in, const int* in_sizes, int n_in,
                              void* d_out, int out_size)
{
    const float* q = (const float*)d_in[0];
    const float* k = (const float*)d_in[1];
    float* out = (float*)d_out;
    float* S = out;  // scores1 region at offset 0

    dim3 gGemm(N_ / TBN, N_ / TBM, B_);
    gemm_qkT_kernel<<<gGemm, 256>>>(q, k, S);

    combine_kernel<<<B_ * N_ / 128, 128>>>(S);

    topk_inst_kernel<<<B_, 1024>>>();

    select_kernel<<<B_ * K_ / 8, 256>>>(S, out);

    emit_kernel<<<B_ * K_ * R_ / 8, 256>>>(q, out);
}

// round 4
// speedup vs baseline: 1.7313x; 1.2912x over previous
#include <cuda_runtime.h>
#include <math.h>
#include <stdint.h>

#define B_ 8
#define N_ 2048
#define D_ 256
#define K_ 512
#define R_ 32
#define NSEG 64      // N_ / 32 column segments for softmax partials

// GEMM tiling
#define TM 128
#define TN 128
#define BK 32
#define NCHUNKS (D_ / BK)   // 8

// Output packing: scores1 [B,N,N] | soi [B,K*R,3] | rel_e [B,K*R,D], all float32
static constexpr size_t SCORES_ELEMS = (size_t)B_ * N_ * N_;
static constexpr size_t SOI_OFF      = SCORES_ELEMS;
static constexpr size_t RELE_OFF     = SOI_OFF + (size_t)B_ * K_ * R_ * 3;

// Scratch (__device__ globals; no allocation allowed)
__device__ float2 g_part[(size_t)B_ * N_ * NSEG];
__device__ float  g_diag[B_ * N_];
__device__ int    g_inst[B_ * K_];
__device__ int    g_obj [B_ * K_ * R_];
__device__ float  g_qhi[(size_t)B_ * N_ * D_];
__device__ float  g_qlo[(size_t)B_ * N_ * D_];
__device__ float  g_khi[(size_t)B_ * N_ * D_];
__device__ float  g_klo[(size_t)B_ * N_ * D_];

// ---------------------------------------------------------------------------
// helpers
// ---------------------------------------------------------------------------
__device__ __forceinline__ uint32_t smem_u32(const void* p) {
    uint32_t a;
    asm("{ .reg .u64 t; cvta.to.shared.u64 t, %1; cvt.u32.u64 %0, t; }" : "=r"(a) : "l"(p));
    return a;
}
__device__ __forceinline__ void cpasync16(uint32_t saddr, const void* g) {
    asm volatile("cp.async.ca.shared.global [%0], [%1], 16;" :: "r"(saddr), "l"(g) : "memory");
}
#define CP_COMMIT() asm volatile("cp.async.commit_group;" ::: "memory")
#define CP_WAIT(n)  asm volatile("cp.async.wait_group %0;" :: "n"(n) : "memory")

__device__ __forceinline__ float tf32_rna(float x) {
    uint32_t u;
    asm("cvt.rna.tf32.f32 %0, %1;" : "=r"(u) : "f"(x));
    return __uint_as_float(u);
}

__device__ __forceinline__ void mma_tf32(float* c, const uint32_t* a, const uint32_t* b) {
    asm volatile(
        "mma.sync.aligned.m16n8k8.row.col.f32.tf32.tf32.f32 "
        "{%0,%1,%2,%3}, {%4,%5,%6,%7}, {%8,%9}, {%0,%1,%2,%3};"
        : "+f"(c[0]), "+f"(c[1]), "+f"(c[2]), "+f"(c[3])
        : "r"(a[0]), "r"(a[1]), "r"(a[2]), "r"(a[3]), "r"(b[0]), "r"(b[1]));
}

// ---------------------------------------------------------------------------
// Kernel 0: split fp32 -> (hi, lo) tf32 pair for q and k
// ---------------------------------------------------------------------------
__global__ __launch_bounds__(256) void decomp_kernel(
    const float* __restrict__ q, const float* __restrict__ k)
{
    const size_t i = (size_t)blockIdx.x * 256 + threadIdx.x;  // float4 index
    float4 x = ((const float4*)q)[i];
    float4 h, l;
    h.x = tf32_rna(x.x); l.x = tf32_rna(x.x - h.x);
    h.y = tf32_rna(x.y); l.y = tf32_rna(x.y - h.y);
    h.z = tf32_rna(x.z); l.z = tf32_rna(x.z - h.z);
    h.w = tf32_rna(x.w); l.w = tf32_rna(x.w - h.w);
    ((float4*)g_qhi)[i] = h; ((float4*)g_qlo)[i] = l;

    x = ((const float4*)k)[i];
    h.x = tf32_rna(x.x); l.x = tf32_rna(x.x - h.x);
    h.y = tf32_rna(x.y); l.y = tf32_rna(x.y - h.y);
    h.z = tf32_rna(x.z); l.z = tf32_rna(x.z - h.z);
    h.w = tf32_rna(x.w); l.w = tf32_rna(x.w - h.w);
    ((float4*)g_khi)[i] = h; ((float4*)g_klo)[i] = l;
}

// ---------------------------------------------------------------------------
// Kernel 1: 3xTF32 GEMM via mma.sync (m16n8k8), 128x128 tile, 512 threads,
// double-buffered cp.async, fused per-32col softmax partials in epilogue.
// smem per stage: A_hi | A_lo | B_hi | B_lo, each 128 rows x 128 bytes.
// ---------------------------------------------------------------------------
static constexpr int S_AHI = 0;
static constexpr int S_ALO = 16384;
static constexpr int S_BHI = 32768;
static constexpr int S_BLO = 49152;
static constexpr int STAGE = 65536;
static constexpr int GEMM_SMEM = 2 * STAGE;   // 128 KB

__global__ __launch_bounds__(512) void gemm_tc_kernel(float* __restrict__ S)
{
    extern __shared__ char smem[];
    const uint32_t sbase = smem_u32(smem);
    const int tid = threadIdx.x;
    const int wid  = tid >> 5;
    const int lane = tid & 31;
    const int g  = lane >> 2;     // groupID 0..7
    const int tg = lane & 3;      // thread-in-group 0..3
    const int wm = (wid >> 2) * 32;   // warp m base in tile
    const int wn = (wid & 3)  * 32;   // warp n base in tile

    const int b  = blockIdx.z;
    const int m0 = blockIdx.y * TM;
    const int n0 = blockIdx.x * TN;

    const float4* qhi4 = (const float4*)(g_qhi + (size_t)b * N_ * D_);
    const float4* qlo4 = (const float4*)(g_qlo + (size_t)b * N_ * D_);
    const float4* khi4 = (const float4*)(g_khi + (size_t)b * N_ * D_);
    const float4* klo4 = (const float4*)(g_klo + (size_t)b * N_ * D_);

    // loader mapping: per stage each array = 128 rows x 8 float4; thread does 2 per array
    const int l_row0 = tid >> 3;            // idx = tid
    const int l_c4_0 = tid & 7;
    const int l_row1 = (tid + 512) >> 3;    // idx = tid + 512
    const int l_c4_1 = tid & 7;             // (tid+512)&7 == tid&7
    const uint32_t l_sw0 = (uint32_t)(l_row0 * 128 + (l_c4_0 * 16 ^ ((l_row0 & 7) << 4)));
    const uint32_t l_sw1 = (uint32_t)(l_row1 * 128 + (l_c4_1 * 16 ^ ((l_row1 & 7) << 4)));

    auto load_stage = [&](int c, int buf) {
        const uint32_t sb = sbase + buf * STAGE;
        const int k4 = c * (BK / 4);
        size_t gA0 = (size_t)(m0 + l_row0) * (D_ / 4) + k4 + l_c4_0;
        size_t gA1 = (size_t)(m0 + l_row1) * (D_ / 4) + k4 + l_c4_1;
        size_t gB0 = (size_t)(n0 + l_row0) * (D_ / 4) + k4 + l_c4_0;
        size_t gB1 = (size_t)(n0 + l_row1) * (D_ / 4) + k4 + l_c4_1;
        cpasync16(sb + S_AHI + l_sw0, qhi4 + gA0);
        cpasync16(sb + S_AHI + l_sw1, qhi4 + gA1);
        cpasync16(sb + S_ALO + l_sw0, qlo4 + gA0);
        cpasync16(sb + S_ALO + l_sw1, qlo4 + gA1);
        cpasync16(sb + S_BHI + l_sw0, khi4 + gB0);
        cpasync16(sb + S_BHI + l_sw1, khi4 + gB1);
        cpasync16(sb + S_BLO + l_sw0, klo4 + gB0);
        cpasync16(sb + S_BLO + l_sw1, klo4 + gB1);
    };

    // fragment row offsets (byte): A rows wm + t*16 + g (+8), B rows wn + u*8 + g
    int ra[2][2], rb[4];
#pragma unroll
    for (int t = 0; t < 2; t++) {
        ra[t][0] = (wm + t * 16 + g) * 128;
        ra[t][1] = (wm + t * 16 + g + 8) * 128;
    }
#pragma unroll
    for (int u = 0; u < 4; u++) rb[u] = (wn + u * 8 + g) * 128;
    const int gx = g << 4;

    float acc[2][4][4];
#pragma unroll
    for (int t = 0; t < 2; t++)
#pragma unroll
        for (int u = 0; u < 4; u++)
#pragma unroll
            for (int r = 0; r < 4; r++) acc[t][u][r] = 0.0f;

    load_stage(0, 0);
    CP_COMMIT();

    for (int c = 0; c < NCHUNKS; c++) {
        if (c + 1 < NCHUNKS) { load_stage(c + 1, (c + 1) & 1); CP_COMMIT(); CP_WAIT(1); }
        else                 { CP_WAIT(0); }
        __syncthreads();

        const char* sb = smem + (c & 1) * STAGE;
#pragma unroll
        for (int ks = 0; ks < 4; ks++) {
            const int kb  = (ks * 8 + tg) * 4;
            const int kx0 = kb ^ gx;
            const int kx1 = (kb + 16) ^ gx;

            uint32_t ahi[2][4], alo[2][4], bhi[4][2], blo[4][2];
#pragma unroll
            for (int t = 0; t < 2; t++) {
                ahi[t][0] = *(const uint32_t*)(sb + S_AHI + ra[t][0] + kx0);
                ahi[t][1] = *(const uint32_t*)(sb + S_AHI + ra[t][1] + kx0);
                ahi[t][2] = *(const uint32_t*)(sb + S_AHI + ra[t][0] + kx1);
                ahi[t][3] = *(const uint32_t*)(sb + S_AHI + ra[t][1] + kx1);
                alo[t][0] = *(const uint32_t*)(sb + S_ALO + ra[t][0] + kx0);
                alo[t][1] = *(const uint32_t*)(sb + S_ALO + ra[t][1] + kx0);
                alo[t][2] = *(const uint32_t*)(sb + S_ALO + ra[t][0] + kx1);
                alo[t][3] = *(const uint32_t*)(sb + S_ALO + ra[t][1] + kx1);
            }
#pragma unroll
            for (int u = 0; u < 4; u++) {
                bhi[u][0] = *(const uint32_t*)(sb + S_BHI + rb[u] + kx0);
                bhi[u][1] = *(const uint32_t*)(sb + S_BHI + rb[u] + kx1);
                blo[u][0] = *(const uint32_t*)(sb + S_BLO + rb[u] + kx0);
                blo[u][1] = *(const uint32_t*)(sb + S_BLO + rb[u] + kx1);
            }
#pragma unroll
            for (int t = 0; t < 2; t++)
#pragma unroll
                for (int u = 0; u < 4; u++) {
                    mma_tf32(acc[t][u], ahi[t], bhi[u]);
                    mma_tf32(acc[t][u], ahi[t], blo[u]);
                    mma_tf32(acc[t][u], alo[t], bhi[u]);
                }
        }
        __syncthreads();
    }

    // Epilogue: store S (float2 per ntile) + softmax partials per (row, 32seg)
    const int seg = (n0 >> 5) + (wid & 3);
#pragma unroll
    for (int t = 0; t < 2; t++) {
#pragma unroll
        for (int h = 0; h < 2; h++) {
            const int row = m0 + wm + t * 16 + g + h * 8;
            float* Sr = S + ((size_t)b * N_ + row) * N_ + n0 + wn;
            float mx = -INFINITY;
#pragma unroll
            for (int u = 0; u < 4; u++) {
                float v0 = acc[t][u][h * 2], v1 = acc[t][u][h * 2 + 1];
                *(float2*)(Sr + u * 8 + tg * 2) = make_float2(v0, v1);
                mx = fmaxf(mx, fmaxf(v0, v1));
            }
            mx = fmaxf(mx, __shfl_xor_sync(0xffffffffu, mx, 1));
            mx = fmaxf(mx, __shfl_xor_sync(0xffffffffu, mx, 2));
            float sm = 0.0f;
#pragma unroll
            for (int u = 0; u < 4; u++)
                sm += expf(acc[t][u][h * 2] - mx) + expf(acc[t][u][h * 2 + 1] - mx);
            sm += __shfl_xor_sync(0xffffffffu, sm, 1);
            sm += __shfl_xor_sync(0xffffffffu, sm, 2);
            if (tg == 0)
                g_part[((size_t)b * N_ + row) * NSEG + seg] = make_float2(mx, sm);
        }
    }
}

// ---------------------------------------------------------------------------
// Kernel 2: combine per-seg partials -> diagonal softmax prob per row
// one warp per row
// ---------------------------------------------------------------------------
__global__ __launch_bounds__(256) void combine_kernel(const float* __restrict__ S)
{
    const int row  = blockIdx.x * 8 + (threadIdx.x >> 5);
    const int lane = threadIdx.x & 31;
    const float2* p = g_part + (size_t)row * NSEG;
    float2 p0 = p[lane], p1 = p[lane + 32];
    float m = fmaxf(p0.x, p1.x);
#pragma unroll
    for (int o = 16; o > 0; o >>= 1) m = fmaxf(m, __shfl_xor_sync(0xffffffffu, m, o));
    float Z = p0.y * expf(p0.x - m) + p1.y * expf(p1.x - m);
#pragma unroll
    for (int o = 16; o > 0; o >>= 1) Z += __shfl_xor_sync(0xffffffffu, Z, o);
    if (lane == 0) {
        const int i = row & (N_ - 1);
        g_diag[row] = expf(S[(size_t)row * N_ + i] - m) / Z;
    }
}

// ---------------------------------------------------------------------------
// Kernel 3: per-batch top-512 of diag, sorted ascending indices
// ---------------------------------------------------------------------------
__global__ __launch_bounds__(1024) void topk_inst_kernel()
{
    __shared__ float v[N_];
    __shared__ int   id[N_];
    __shared__ int   sel[K_];

    const int b   = blockIdx.x;
    const int tid = threadIdx.x;

    for (int i = tid; i < N_; i += 1024) { v[i] = g_diag[b * N_ + i]; id[i] = i; }
    __syncthreads();

    for (int k = 2; k <= N_; k <<= 1) {
        for (int j = k >> 1; j > 0; j >>= 1) {
            for (int i = tid; i < N_; i += 1024) {
                int ixj = i ^ j;
                if (ixj > i) {
                    float vi = v[i], vx = v[ixj];
                    int ii = id[i], ix = id[ixj];
                    bool beforeXI = (vx > vi) || (vx == vi && ix < ii);
                    bool dir = ((i & k) == 0);
                    if (beforeXI == dir) {
                        v[i] = vx; v[ixj] = vi; id[i] = ix; id[ixj] = ii;
                    }
                }
            }
            __syncthreads();
        }
    }

    if (tid < K_) sel[tid] = id[tid];
    __syncthreads();

    for (int k = 2; k <= K_; k <<= 1) {
        for (int j = k >> 1; j > 0; j >>= 1) {
            for (int i = tid; i < K_; i += 1024) {
                int ixj = i ^ j;
                if (ixj > i) {
                    int a = sel[i], c = sel[ixj];
                    bool beforeXI = (c < a);
                    bool dir = ((i & k) == 0);
                    if (beforeXI == dir) { sel[i] = c; sel[ixj] = a; }
                }
            }
            __syncthreads();
        }
    }

    if (tid < K_) g_inst[b * K_ + tid] = sel[tid];
}

// ---------------------------------------------------------------------------
// Kernel 4: warp-level top-32 selection per (b,a)
// ---------------------------------------------------------------------------
__device__ __forceinline__ bool kv_before(float va, int ia, float vb, int ib) {
    return (va > vb) || (va == vb && ia < ib);
}

__global__ __launch_bounds__(256) void select_kernel(
    const float* __restrict__ S, float* __restrict__ out)
{
    const int warp = threadIdx.x >> 5;
    const int lane = threadIdx.x & 31;
    const int b = blockIdx.x >> 6;
    const int a = ((blockIdx.x & 63) << 3) + warp;

    __shared__ int s_inst[K_];
    for (int c = threadIdx.x; c < K_; c += 256) s_inst[c] = g_inst[b * K_ + c];
    __syncthreads();

    const int ia = s_inst[a];
    const float* Srow = S + ((size_t)b * N_ + ia) * N_;

    float v; int idx;

    {
        int c = lane;
        float x = Srow[s_inst[c]];
        if (c == a) x = __int_as_float(0x7f800000);
        v = x; idx = c;
#pragma unroll
        for (int k = 2; k <= 32; k <<= 1) {
#pragma unroll
            for (int j = k >> 1; j > 0; j >>= 1) {
                float pv = __shfl_xor_sync(0xffffffffu, v, j);
                int   pi = __shfl_xor_sync(0xffffffffu, idx, j);
                bool desc  = ((lane & k) == 0);
                bool lower = ((lane & j) == 0);
                bool win = kv_before(v, idx, pv, pi);
                bool take = (desc == lower) ? !win : win;
                if (take) { v = pv; idx = pi; }
            }
        }
    }

    for (int t = 1; t < 16; t++) {
        int c = t * 32 + lane;
        float v2 = Srow[s_inst[c]];
        if (c == a) v2 = __int_as_float(0x7f800000);
        int i2 = c;
#pragma unroll
        for (int k = 2; k <= 32; k <<= 1) {
#pragma unroll
            for (int j = k >> 1; j > 0; j >>= 1) {
                float pv = __shfl_xor_sync(0xffffffffu, v2, j);
                int   pi = __shfl_xor_sync(0xffffffffu, i2, j);
                bool desc  = ((lane & k) == 0);
                bool lower = ((lane & j) == 0);
                bool win = kv_before(v2, i2, pv, pi);
                bool take = (desc == lower) ? !win : win;
                if (take) { v2 = pv; i2 = pi; }
            }
        }
        float cv = __shfl_xor_sync(0xffffffffu, v2, 31);
        int   ci = __shfl_xor_sync(0xffffffffu, i2, 31);
        if (!kv_before(v, idx, cv, ci)) { v = cv; idx = ci; }
#pragma unroll
        for (int j = 16; j > 0; j >>= 1) {
            float pv = __shfl_xor_sync(0xffffffffu, v, j);
            int   pi = __shfl_xor_sync(0xffffffffu, idx, j);
            bool lower = ((lane & j) == 0);
            bool win = kv_before(v, idx, pv, pi);
            bool take = lower ? !win : win;
            if (take) { v = pv; idx = pi; }
        }
    }

#pragma unroll
    for (int k = 2; k <= 32; k <<= 1) {
#pragma unroll
        for (int j = k >> 1; j > 0; j >>= 1) {
            int pi = __shfl_xor_sync(0xffffffffu, idx, j);
            bool asc   = ((lane & k) == 0);
            bool lower = ((lane & j) == 0);
            bool win = (idx < pi);
            bool take = (asc == lower) ? !win : win;
            if (take) idx = pi;
        }
    }

    const int obj = s_inst[idx];
    const size_t base = (size_t)b * K_ + a;
    g_obj[base * R_ + lane] = obj;
    float* soi = out + SOI_OFF + base * R_ * 3 + lane * 3;
    soi[0] = (float)b;
    soi[1] = (float)ia;
    soi[2] = (float)obj;
}

// ---------------------------------------------------------------------------
// Kernel 5: emit rel_e (one warp per relation)
// ---------------------------------------------------------------------------
__global__ __launch_bounds__(256) void emit_kernel(
    const float* __restrict__ Q, float* __restrict__ out)
{
    const int rel  = blockIdx.x * 8 + (threadIdx.x >> 5);
    const int lane = threadIdx.x & 31;
    const int b   = rel >> 14;
    const int rem = rel & 16383;
    const int a   = rem >> 5;
    const int ia  = g_inst[b * K_ + a];
    const int obj = g_obj[rel];

    const float4* qa = (const float4*)(Q + ((size_t)b * N_ + ia)  * D_) + lane * 2;
    const float4* qo = (const float4*)(Q + ((size_t)b * N_ + obj) * D_) + lane * 2;
    float4 x0 = qa[0], x1 = qa[1];
    float4 y0 = qo[0], y1 = qo[1];
    x0.x += y0.x; x0.y += y0.y; x0.z += y0.z; x0.w += y0.w;
    x1.x += y1.x; x1.y += y1.y; x1.z += y1.z; x1.w += y1.w;

    float s = x0.x + x0.y + x0.z + x0.w + x1.x + x1.y + x1.z + x1.w;
#pragma unroll
    for (int o = 16; o > 0; o >>= 1) s += __shfl_xor_sync(0xffffffffu, s, o);
    const float mu = s * (1.0f / 256.0f);

    float d0x = x0.x - mu, d0y = x0.y - mu, d0z = x0.z - mu, d0w = x0.w - mu;
    float d1x = x1.x - mu, d1y = x1.y - mu, d1z = x1.z - mu, d1w = x1.w - mu;
    float s2 = d0x*d0x + d0y*d0y + d0z*d0z + d0w*d0w
             + d1x*d1x + d1y*d1y + d1z*d1z + d1w*d1w;
#pragma unroll
    for (int o = 16; o > 0; o >>= 1) s2 += __shfl_xor_sync(0xffffffffu, s2, o);
    const float r = rsqrtf(s2 * (1.0f / 256.0f) + 1e-5f);

    float4* o4 = (float4*)(out + RELE_OFF + (size_t)rel * D_) + lane * 2;
    o4[0] = make_float4(d0x * r, d0y * r, d0z * r, d0w * r);
    o4[1] = make_float4(d1x * r, d1y * r, d1z * r, d1w * r);
}

// ---------------------------------------------------------------------------
extern "C" void kernel_launch(void* const* d_in, const int* in_sizes, int n_in,
                              void* d_out, int out_size)
{
    const float* q = (const float*)d_in[0];
    const float* k = (const float*)d_in[1];
    float* out = (float*)d_out;
    float* S = out;

    cudaFuncSetAttribute(gemm_tc_kernel,
                         cudaFuncAttributeMaxDynamicSharedMemorySize, GEMM_SMEM);

    decomp_kernel<<<(B_ * N_ * D_ / 4) / 256, 256>>>(q, k);

    dim3 gGemm(N_ / TN, N_ / TM, B_);
    gemm_tc_kernel<<<gGemm, 512, GEMM_SMEM>>>(S);

    combine_kernel<<<B_ * N_ / 8, 256>>>(S);

    topk_inst_kernel<<<B_, 1024>>>();

    select_kernel<<<B_ * K_ / 8, 256>>>(S, out);

    emit_kernel<<<B_ * K_ * R_ / 8, 256>>>(q, out);
}

// round 5
// speedup vs baseline: 2.5588x; 1.4779x over previous
#include <cuda_runtime.h>
#include <cuda_fp16.h>
#include <math.h>
#include <stdint.h>

#define B_ 8
#define N_ 2048
#define D_ 256
#define K_ 512
#define R_ 32
#define NSEG 64      // N_ / 32 column segments for softmax partials

// GEMM tiling
#define TM 128
#define TN 128
#define BK 64
#define NCHUNKS (D_ / BK)   // 4

// Output packing: scores1 [B,N,N] | soi [B,K*R,3] | rel_e [B,K*R,D], all float32
static constexpr size_t SCORES_ELEMS = (size_t)B_ * N_ * N_;
static constexpr size_t SOI_OFF      = SCORES_ELEMS;
static constexpr size_t RELE_OFF     = SOI_OFF + (size_t)B_ * K_ * R_ * 3;

// Scratch (__device__ globals; no allocation allowed)
__device__ float2 g_part[(size_t)B_ * N_ * NSEG];
__device__ float  g_diag[B_ * N_];
__device__ int    g_inst[B_ * K_];
__device__ int    g_obj [B_ * K_ * R_];
__device__ __half g_qhi[(size_t)B_ * N_ * D_];
__device__ __half g_qlo[(size_t)B_ * N_ * D_];
__device__ __half g_khi[(size_t)B_ * N_ * D_];
__device__ __half g_klo[(size_t)B_ * N_ * D_];

// ---------------------------------------------------------------------------
// helpers
// ---------------------------------------------------------------------------
__device__ __forceinline__ uint32_t smem_u32(const void* p) {
    uint32_t a;
    asm("{ .reg .u64 t; cvta.to.shared.u64 t, %1; cvt.u32.u64 %0, t; }" : "=r"(a) : "l"(p));
    return a;
}
__device__ __forceinline__ void cpasync16(uint32_t saddr, const void* g) {
    asm volatile("cp.async.ca.shared.global [%0], [%1], 16;" :: "r"(saddr), "l"(g) : "memory");
}
#define CP_COMMIT() asm volatile("cp.async.commit_group;" ::: "memory")
#define CP_WAIT(n)  asm volatile("cp.async.wait_group %0;" :: "n"(n) : "memory")

__device__ __forceinline__ void mma_f16(float* c, const uint32_t* a, const uint32_t* b) {
    asm volatile(
        "mma.sync.aligned.m16n8k16.row.col.f32.f16.f16.f32 "
        "{%0,%1,%2,%3}, {%4,%5,%6,%7}, {%8,%9}, {%0,%1,%2,%3};"
        : "+f"(c[0]), "+f"(c[1]), "+f"(c[2]), "+f"(c[3])
        : "r"(a[0]), "r"(a[1]), "r"(a[2]), "r"(a[3]), "r"(b[0]), "r"(b[1]));
}

// ---------------------------------------------------------------------------
// Kernel 0: split fp32 -> (hi, lo) fp16 pair for q and k
// ---------------------------------------------------------------------------
__global__ __launch_bounds__(256) void decomp_kernel(
    const float* __restrict__ q, const float* __restrict__ k)
{
    const size_t i = (size_t)blockIdx.x * 256 + threadIdx.x;  // float4 index
    {
        float4 x = ((const float4*)q)[i];
        __half h0 = __float2half_rn(x.x), h1 = __float2half_rn(x.y);
        __half h2 = __float2half_rn(x.z), h3 = __float2half_rn(x.w);
        __half l0 = __float2half_rn(x.x - __half2float(h0));
        __half l1 = __float2half_rn(x.y - __half2float(h1));
        __half l2 = __float2half_rn(x.z - __half2float(h2));
        __half l3 = __float2half_rn(x.w - __half2float(h3));
        __half2 hh0 = __halves2half2(h0, h1), hh1 = __halves2half2(h2, h3);
        __half2 ll0 = __halves2half2(l0, l1), ll1 = __halves2half2(l2, l3);
        uint2 ho = make_uint2(*(uint32_t*)&hh0, *(uint32_t*)&hh1);
        uint2 lo = make_uint2(*(uint32_t*)&ll0, *(uint32_t*)&ll1);
        ((uint2*)g_qhi)[i] = ho; ((uint2*)g_qlo)[i] = lo;
    }
    {
        float4 x = ((const float4*)k)[i];
        __half h0 = __float2half_rn(x.x), h1 = __float2half_rn(x.y);
        __half h2 = __float2half_rn(x.z), h3 = __float2half_rn(x.w);
        __half l0 = __float2half_rn(x.x - __half2float(h0));
        __half l1 = __float2half_rn(x.y - __half2float(h1));
        __half l2 = __float2half_rn(x.z - __half2float(h2));
        __half l3 = __float2half_rn(x.w - __half2float(h3));
        __half2 hh0 = __halves2half2(h0, h1), hh1 = __halves2half2(h2, h3);
        __half2 ll0 = __halves2half2(l0, l1), ll1 = __halves2half2(l2, l3);
        uint2 ho = make_uint2(*(uint32_t*)&hh0, *(uint32_t*)&hh1);
        uint2 lo = make_uint2(*(uint32_t*)&ll0, *(uint32_t*)&ll1);
        ((uint2*)g_khi)[i] = ho; ((uint2*)g_klo)[i] = lo;
    }
}

// ---------------------------------------------------------------------------
// Kernel 1: 3xFP16 GEMM via mma.sync (m16n8k16), 128x128 tile, 512 threads,
// double-buffered cp.async, fused per-32col softmax partials in epilogue.
// smem per stage: A_hi | A_lo | B_hi | B_lo, each 128 rows x 128 bytes (64 fp16).
// ---------------------------------------------------------------------------
static constexpr int S_AHI = 0;
static constexpr int S_ALO = 16384;
static constexpr int S_BHI = 32768;
static constexpr int S_BLO = 49152;
static constexpr int STAGE = 65536;
static constexpr int GEMM_SMEM = 2 * STAGE;   // 128 KB

__global__ __launch_bounds__(512) void gemm_tc_kernel(float* __restrict__ S)
{
    extern __shared__ char smem[];
    const uint32_t sbase = smem_u32(smem);
    const int tid = threadIdx.x;
    const int wid  = tid >> 5;
    const int lane = tid & 31;
    const int g  = lane >> 2;     // groupID 0..7
    const int tg = lane & 3;      // thread-in-group 0..3
    const int wm = (wid >> 2) * 32;   // warp m base in tile
    const int wn = (wid & 3)  * 32;   // warp n base in tile

    const int b  = blockIdx.z;
    const int m0 = blockIdx.y * TM;
    const int n0 = blockIdx.x * TN;

    const uint4* qhi4 = (const uint4*)(g_qhi + (size_t)b * N_ * D_);
    const uint4* qlo4 = (const uint4*)(g_qlo + (size_t)b * N_ * D_);
    const uint4* khi4 = (const uint4*)(g_khi + (size_t)b * N_ * D_);
    const uint4* klo4 = (const uint4*)(g_klo + (size_t)b * N_ * D_);

    // loader: per stage each array = 128 rows x 8 uint4 (128B/row); 2 per thread
    const int l_row0 = tid >> 3;            // idx = tid
    const int l_c4   = tid & 7;
    const int l_row1 = (tid + 512) >> 3;    // idx = tid + 512
    const uint32_t l_sw0 = (uint32_t)(l_row0 * 128 + (l_c4 * 16 ^ ((l_row0 & 7) << 4)));
    const uint32_t l_sw1 = (uint32_t)(l_row1 * 128 + (l_c4 * 16 ^ ((l_row1 & 7) << 4)));

    auto load_stage = [&](int c, int buf) {
        const uint32_t sb = sbase + buf * STAGE;
        const int k4 = c * 8;   // 8 uint4 per row per 64-k chunk
        size_t gA0 = (size_t)(m0 + l_row0) * 32 + k4 + l_c4;   // row stride: 256 fp16 = 32 uint4
        size_t gA1 = (size_t)(m0 + l_row1) * 32 + k4 + l_c4;
        size_t gB0 = (size_t)(n0 + l_row0) * 32 + k4 + l_c4;
        size_t gB1 = (size_t)(n0 + l_row1) * 32 + k4 + l_c4;
        cpasync16(sb + S_AHI + l_sw0, qhi4 + gA0);
        cpasync16(sb + S_AHI + l_sw1, qhi4 + gA1);
        cpasync16(sb + S_ALO + l_sw0, qlo4 + gA0);
        cpasync16(sb + S_ALO + l_sw1, qlo4 + gA1);
        cpasync16(sb + S_BHI + l_sw0, khi4 + gB0);
        cpasync16(sb + S_BHI + l_sw1, khi4 + gB1);
        cpasync16(sb + S_BLO + l_sw0, klo4 + gB0);
        cpasync16(sb + S_BLO + l_sw1, klo4 + gB1);
    };

    // fragment row byte offsets: A rows wm + t*16 + g (+8), B rows wn + u*8 + g
    int ra[2][2], rb[4];
#pragma unroll
    for (int t = 0; t < 2; t++) {
        ra[t][0] = (wm + t * 16 + g) * 128;
        ra[t][1] = (wm + t * 16 + g + 8) * 128;
    }
#pragma unroll
    for (int u = 0; u < 4; u++) rb[u] = (wn + u * 8 + g) * 128;
    const int gx = g << 4;   // swizzle xor (row&7 == g for all fragment rows)

    float acc[2][4][4];
#pragma unroll
    for (int t = 0; t < 2; t++)
#pragma unroll
        for (int u = 0; u < 4; u++)
#pragma unroll
            for (int r = 0; r < 4; r++) acc[t][u][r] = 0.0f;

    load_stage(0, 0);
    CP_COMMIT();

    for (int c = 0; c < NCHUNKS; c++) {
        if (c + 1 < NCHUNKS) { load_stage(c + 1, (c + 1) & 1); CP_COMMIT(); CP_WAIT(1); }
        else                 { CP_WAIT(0); }
        __syncthreads();

        const char* sb = smem + (c & 1) * STAGE;
#pragma unroll
        for (int ks = 0; ks < 4; ks++) {   // k16 steps within 64-k chunk
            const int kb  = ks * 32 + tg * 4;      // byte offset of k-pair (2 fp16)
            const int kx0 = kb ^ gx;
            const int kx1 = (kb + 16) ^ gx;

            uint32_t ahi[2][4], alo[2][4], bhi[4][2], blo[4][2];
#pragma unroll
            for (int t = 0; t < 2; t++) {
                ahi[t][0] = *(const uint32_t*)(sb + S_AHI + ra[t][0] + kx0);
                ahi[t][1] = *(const uint32_t*)(sb + S_AHI + ra[t][1] + kx0);
                ahi[t][2] = *(const uint32_t*)(sb + S_AHI + ra[t][0] + kx1);
                ahi[t][3] = *(const uint32_t*)(sb + S_AHI + ra[t][1] + kx1);
                alo[t][0] = *(const uint32_t*)(sb + S_ALO + ra[t][0] + kx0);
                alo[t][1] = *(const uint32_t*)(sb + S_ALO + ra[t][1] + kx0);
                alo[t][2] = *(const uint32_t*)(sb + S_ALO + ra[t][0] + kx1);
                alo[t][3] = *(const uint32_t*)(sb + S_ALO + ra[t][1] + kx1);
            }
#pragma unroll
            for (int u = 0; u < 4; u++) {
                bhi[u][0] = *(const uint32_t*)(sb + S_BHI + rb[u] + kx0);
                bhi[u][1] = *(const uint32_t*)(sb + S_BHI + rb[u] + kx1);
                blo[u][0] = *(const uint32_t*)(sb + S_BLO + rb[u] + kx0);
                blo[u][1] = *(const uint32_t*)(sb + S_BLO + rb[u] + kx1);
            }
#pragma unroll
            for (int t = 0; t < 2; t++)
#pragma unroll
                for (int u = 0; u < 4; u++) {
                    mma_f16(acc[t][u], ahi[t], bhi[u]);
                    mma_f16(acc[t][u], ahi[t], blo[u]);
                    mma_f16(acc[t][u], alo[t], bhi[u]);
                }
        }
        __syncthreads();
    }

    // Epilogue: store S (float2 per ntile) + softmax partials per (row, 32seg)
    const int seg = (n0 >> 5) + (wid & 3);
#pragma unroll
    for (int t = 0; t < 2; t++) {
#pragma unroll
        for (int h = 0; h < 2; h++) {
            const int row = m0 + wm + t * 16 + g + h * 8;
            float* Sr = S + ((size_t)b * N_ + row) * N_ + n0 + wn;
            float mx = -INFINITY;
#pragma unroll
            for (int u = 0; u < 4; u++) {
                float v0 = acc[t][u][h * 2], v1 = acc[t][u][h * 2 + 1];
                *(float2*)(Sr + u * 8 + tg * 2) = make_float2(v0, v1);
                mx = fmaxf(mx, fmaxf(v0, v1));
            }
            mx = fmaxf(mx, __shfl_xor_sync(0xffffffffu, mx, 1));
            mx = fmaxf(mx, __shfl_xor_sync(0xffffffffu, mx, 2));
            float sm = 0.0f;
#pragma unroll
            for (int u = 0; u < 4; u++)
                sm += expf(acc[t][u][h * 2] - mx) + expf(acc[t][u][h * 2 + 1] - mx);
            sm += __shfl_xor_sync(0xffffffffu, sm, 1);
            sm += __shfl_xor_sync(0xffffffffu, sm, 2);
            if (tg == 0)
                g_part[((size_t)b * N_ + row) * NSEG + seg] = make_float2(mx, sm);
        }
    }
}

// ---------------------------------------------------------------------------
// Kernel 2: combine per-seg partials -> diagonal softmax prob per row
// ---------------------------------------------------------------------------
__global__ __launch_bounds__(256) void combine_kernel(const float* __restrict__ S)
{
    const int row  = blockIdx.x * 8 + (threadIdx.x >> 5);
    const int lane = threadIdx.x & 31;
    const float2* p = g_part + (size_t)row * NSEG;
    float2 p0 = p[lane], p1 = p[lane + 32];
    float m = fmaxf(p0.x, p1.x);
#pragma unroll
    for (int o = 16; o > 0; o >>= 1) m = fmaxf(m, __shfl_xor_sync(0xffffffffu, m, o));
    float Z = p0.y * expf(p0.x - m) + p1.y * expf(p1.x - m);
#pragma unroll
    for (int o = 16; o > 0; o >>= 1) Z += __shfl_xor_sync(0xffffffffu, Z, o);
    if (lane == 0) {
        const int i = row & (N_ - 1);
        g_diag[row] = expf(S[(size_t)row * N_ + i] - m) / Z;
    }
}

// ---------------------------------------------------------------------------
// Kernel 3: per-batch top-512 of diag, sorted ascending indices
// ---------------------------------------------------------------------------
__global__ __launch_bounds__(1024) void topk_inst_kernel()
{
    __shared__ float v[N_];
    __shared__ int   id[N_];
    __shared__ int   sel[K_];

    const int b   = blockIdx.x;
    const int tid = threadIdx.x;

    for (int i = tid; i < N_; i += 1024) { v[i] = g_diag[b * N_ + i]; id[i] = i; }
    __syncthreads();

    for (int k = 2; k <= N_; k <<= 1) {
        for (int j = k >> 1; j > 0; j >>= 1) {
            for (int i = tid; i < N_; i += 1024) {
                int ixj = i ^ j;
                if (ixj > i) {
                    float vi = v[i], vx = v[ixj];
                    int ii = id[i], ix = id[ixj];
                    bool beforeXI = (vx > vi) || (vx == vi && ix < ii);
                    bool dir = ((i & k) == 0);
                    if (beforeXI == dir) {
                        v[i] = vx; v[ixj] = vi; id[i] = ix; id[ixj] = ii;
                    }
                }
            }
            __syncthreads();
        }
    }

    if (tid < K_) sel[tid] = id[tid];
    __syncthreads();

    for (int k = 2; k <= K_; k <<= 1) {
        for (int j = k >> 1; j > 0; j >>= 1) {
            for (int i = tid; i < K_; i += 1024) {
                int ixj = i ^ j;
                if (ixj > i) {
                    int a = sel[i], c = sel[ixj];
                    bool beforeXI = (c < a);
                    bool dir = ((i & k) == 0);
                    if (beforeXI == dir) { sel[i] = c; sel[ixj] = a; }
                }
            }
            __syncthreads();
        }
    }

    if (tid < K_) g_inst[b * K_ + tid] = sel[tid];
}

// ---------------------------------------------------------------------------
// Kernel 4: warp-level top-32 selection per (b,a)
// ---------------------------------------------------------------------------
__device__ __forceinline__ bool kv_before(float va, int ia, float vb, int ib) {
    return (va > vb) || (va == vb && ia < ib);
}

__global__ __launch_bounds__(256) void select_kernel(
    const float* __restrict__ S, float* __restrict__ out)
{
    const int warp = threadIdx.x >> 5;
    const int lane = threadIdx.x & 31;
    const int b = blockIdx.x >> 6;
    const int a = ((blockIdx.x & 63) << 3) + warp;

    __shared__ int s_inst[K_];
    for (int c = threadIdx.x; c < K_; c += 256) s_inst[c] = g_inst[b * K_ + c];
    __syncthreads();

    const int ia = s_inst[a];
    const float* Srow = S + ((size_t)b * N_ + ia) * N_;

    float v; int idx;

    {
        int c = lane;
        float x = Srow[s_inst[c]];
        if (c == a) x = __int_as_float(0x7f800000);
        v = x; idx = c;
#pragma unroll
        for (int k = 2; k <= 32; k <<= 1) {
#pragma unroll
            for (int j = k >> 1; j > 0; j >>= 1) {
                float pv = __shfl_xor_sync(0xffffffffu, v, j);
                int   pi = __shfl_xor_sync(0xffffffffu, idx, j);
                bool desc  = ((lane & k) == 0);
                bool lower = ((lane & j) == 0);
                bool win = kv_before(v, idx, pv, pi);
                bool take = (desc == lower) ? !win : win;
                if (take) { v = pv; idx = pi; }
            }
        }
    }

    for (int t = 1; t < 16; t++) {
        int c = t * 32 + lane;
        float v2 = Srow[s_inst[c]];
        if (c == a) v2 = __int_as_float(0x7f800000);
        int i2 = c;
#pragma unroll
        for (int k = 2; k <= 32; k <<= 1) {
#pragma unroll
            for (int j = k >> 1; j > 0; j >>= 1) {
                float pv = __shfl_xor_sync(0xffffffffu, v2, j);
                int   pi = __shfl_xor_sync(0xffffffffu, i2, j);
                bool desc  = ((lane & k) == 0);
                bool lower = ((lane & j) == 0);
                bool win = kv_before(v2, i2, pv, pi);
                bool take = (desc == lower) ? !win : win;
                if (take) { v2 = pv; i2 = pi; }
            }
        }
        float cv = __shfl_xor_sync(0xffffffffu, v2, 31);
        int   ci = __shfl_xor_sync(0xffffffffu, i2, 31);
        if (!kv_before(v, idx, cv, ci)) { v = cv; idx = ci; }
#pragma unroll
        for (int j = 16; j > 0; j >>= 1) {
            float pv = __shfl_xor_sync(0xffffffffu, v, j);
            int   pi = __shfl_xor_sync(0xffffffffu, idx, j);
            bool lower = ((lane & j) == 0);
            bool win = kv_before(v, idx, pv, pi);
            bool take = lower ? !win : win;
            if (take) { v = pv; idx = pi; }
        }
    }

#pragma unroll
    for (int k = 2; k <= 32; k <<= 1) {
#pragma unroll
        for (int j = k >> 1; j > 0; j >>= 1) {
            int pi = __shfl_xor_sync(0xffffffffu, idx, j);
            bool asc   = ((lane & k) == 0);
            bool lower = ((lane & j) == 0);
            bool win = (idx < pi);
            bool take = (asc == lower) ? !win : win;
            if (take) idx = pi;
        }
    }

    const int obj = s_inst[idx];
    const size_t base = (size_t)b * K_ + a;
    g_obj[base * R_ + lane] = obj;
    float* soi = out + SOI_OFF + base * R_ * 3 + lane * 3;
    soi[0] = (float)b;
    soi[1] = (float)ia;
    soi[2] = (float)obj;
}

// ---------------------------------------------------------------------------
// Kernel 5: emit rel_e (one warp per relation)
// ---------------------------------------------------------------------------
__global__ __launch_bounds__(256) void emit_kernel(
    const float* __restrict__ Q, float* __restrict__ out)
{
    const int rel  = blockIdx.x * 8 + (threadIdx.x >> 5);
    const int lane = threadIdx.x & 31;
    const int b   = rel >> 14;
    const int rem = rel & 16383;
    const int a   = rem >> 5;
    const int ia  = g_inst[b * K_ + a];
    const int obj = g_obj[rel];

    const float4* qa = (const float4*)(Q + ((size_t)b * N_ + ia)  * D_) + lane * 2;
    const float4* qo = (const float4*)(Q + ((size_t)b * N_ + obj) * D_) + lane * 2;
    float4 x0 = qa[0], x1 = qa[1];
    float4 y0 = qo[0], y1 = qo[1];
    x0.x += y0.x; x0.y += y0.y; x0.z += y0.z; x0.w += y0.w;
    x1.x += y1.x; x1.y += y1.y; x1.z += y1.z; x1.w += y1.w;

    float s = x0.x + x0.y + x0.z + x0.w + x1.x + x1.y + x1.z + x1.w;
#pragma unroll
    for (int o = 16; o > 0; o >>= 1) s += __shfl_xor_sync(0xffffffffu, s, o);
    const float mu = s * (1.0f / 256.0f);

    float d0x = x0.x - mu, d0y = x0.y - mu, d0z = x0.z - mu, d0w = x0.w - mu;
    float d1x = x1.x - mu, d1y = x1.y - mu, d1z = x1.z - mu, d1w = x1.w - mu;
    float s2 = d0x*d0x + d0y*d0y + d0z*d0z + d0w*d0w
             + d1x*d1x + d1y*d1y + d1z*d1z + d1w*d1w;
#pragma unroll
    for (int o = 16; o > 0; o >>= 1) s2 += __shfl_xor_sync(0xffffffffu, s2, o);
    const float r = rsqrtf(s2 * (1.0f / 256.0f) + 1e-5f);

    float4* o4 = (float4*)(out + RELE_OFF + (size_t)rel * D_) + lane * 2;
    o4[0] = make_float4(d0x * r, d0y * r, d0z * r, d0w * r);
    o4[1] = make_float4(d1x * r, d1y * r, d1z * r, d1w * r);
}

// ---------------------------------------------------------------------------
extern "C" void kernel_launch(void* const* d_in, const int* in_sizes, int n_in,
                              void* d_out, int out_size)
{
    const float* q = (const float*)d_in[0];
    const float* k = (const float*)d_in[1];
    float* out = (float*)d_out;
    float* S = out;

    cudaFuncSetAttribute(gemm_tc_kernel,
                         cudaFuncAttributeMaxDynamicSharedMemorySize, GEMM_SMEM);

    decomp_kernel<<<(B_ * N_ * D_ / 4) / 256, 256>>>(q, k);

    dim3 gGemm(N_ / TN, N_ / TM, B_);
    gemm_tc_kernel<<<gGemm, 512, GEMM_SMEM>>>(S);

    combine_kernel<<<B_ * N_ / 8, 256>>>(S);

    topk_inst_kernel<<<B_, 1024>>>();

    select_kernel<<<B_ * K_ / 8, 256>>>(S, out);

    emit_kernel<<<B_ * K_ * R_ / 8, 256>>>(q, out);
}

// round 6
// speedup vs baseline: 2.6585x; 1.0390x over previous
#include <cuda_runtime.h>
#include <cuda_fp16.h>
#include <math.h>
#include <stdint.h>

#define B_ 8
#define N_ 2048
#define D_ 256
#define K_ 512
#define R_ 32
#define NSEG 64      // N_ / 32 column segments for softmax partials

// GEMM tiling
#define TM 128
#define TN 128
#define BK 64
#define NCHUNKS (D_ / BK)   // 4

// Output packing: scores1 [B,N,N] | soi [B,K*R,3] | rel_e [B,K*R,D], all float32
static constexpr size_t SCORES_ELEMS = (size_t)B_ * N_ * N_;
static constexpr size_t SOI_OFF      = SCORES_ELEMS;
static constexpr size_t RELE_OFF     = SOI_OFF + (size_t)B_ * K_ * R_ * 3;

// Scratch (__device__ globals; no allocation allowed)
__device__ float2 g_part[(size_t)B_ * N_ * NSEG];
__device__ float  g_diag[B_ * N_];
__device__ int    g_flag[B_ * N_];
__device__ int    g_inst[B_ * K_];
__device__ int    g_obj [B_ * K_ * R_];
__device__ __half g_qhi[(size_t)B_ * N_ * D_];
__device__ __half g_qlo[(size_t)B_ * N_ * D_];
__device__ __half g_khi[(size_t)B_ * N_ * D_];
__device__ __half g_klo[(size_t)B_ * N_ * D_];

// ---------------------------------------------------------------------------
// helpers
// ---------------------------------------------------------------------------
__device__ __forceinline__ uint32_t smem_u32(const void* p) {
    uint32_t a;
    asm("{ .reg .u64 t; cvta.to.shared.u64 t, %1; cvt.u32.u64 %0, t; }" : "=r"(a) : "l"(p));
    return a;
}
__device__ __forceinline__ void cpasync16(uint32_t saddr, const void* g) {
    asm volatile("cp.async.ca.shared.global [%0], [%1], 16;" :: "r"(saddr), "l"(g) : "memory");
}
#define CP_COMMIT() asm volatile("cp.async.commit_group;" ::: "memory")
#define CP_WAIT(n)  asm volatile("cp.async.wait_group %0;" :: "n"(n) : "memory")

__device__ __forceinline__ void mma_f16(float* c, const uint32_t* a, const uint32_t* b) {
    asm volatile(
        "mma.sync.aligned.m16n8k16.row.col.f32.f16.f16.f32 "
        "{%0,%1,%2,%3}, {%4,%5,%6,%7}, {%8,%9}, {%0,%1,%2,%3};"
        : "+f"(c[0]), "+f"(c[1]), "+f"(c[2]), "+f"(c[3])
        : "r"(a[0]), "r"(a[1]), "r"(a[2]), "r"(a[3]), "r"(b[0]), "r"(b[1]));
}

// ---------------------------------------------------------------------------
// Kernel 0: split fp32 -> (hi, lo) fp16 pair for q and k
// ---------------------------------------------------------------------------
__global__ __launch_bounds__(256) void decomp_kernel(
    const float* __restrict__ q, const float* __restrict__ k)
{
    const size_t i = (size_t)blockIdx.x * 256 + threadIdx.x;  // float4 index
    {
        float4 x = ((const float4*)q)[i];
        __half h0 = __float2half_rn(x.x), h1 = __float2half_rn(x.y);
        __half h2 = __float2half_rn(x.z), h3 = __float2half_rn(x.w);
        __half l0 = __float2half_rn(x.x - __half2float(h0));
        __half l1 = __float2half_rn(x.y - __half2float(h1));
        __half l2 = __float2half_rn(x.z - __half2float(h2));
        __half l3 = __float2half_rn(x.w - __half2float(h3));
        __half2 hh0 = __halves2half2(h0, h1), hh1 = __halves2half2(h2, h3);
        __half2 ll0 = __halves2half2(l0, l1), ll1 = __halves2half2(l2, l3);
        uint2 ho = make_uint2(*(uint32_t*)&hh0, *(uint32_t*)&hh1);
        uint2 lo = make_uint2(*(uint32_t*)&ll0, *(uint32_t*)&ll1);
        ((uint2*)g_qhi)[i] = ho; ((uint2*)g_qlo)[i] = lo;
    }
    {
        float4 x = ((const float4*)k)[i];
        __half h0 = __float2half_rn(x.x), h1 = __float2half_rn(x.y);
        __half h2 = __float2half_rn(x.z), h3 = __float2half_rn(x.w);
        __half l0 = __float2half_rn(x.x - __half2float(h0));
        __half l1 = __float2half_rn(x.y - __half2float(h1));
        __half l2 = __float2half_rn(x.z - __half2float(h2));
        __half l3 = __float2half_rn(x.w - __half2float(h3));
        __half2 hh0 = __halves2half2(h0, h1), hh1 = __halves2half2(h2, h3);
        __half2 ll0 = __halves2half2(l0, l1), ll1 = __halves2half2(l2, l3);
        uint2 ho = make_uint2(*(uint32_t*)&hh0, *(uint32_t*)&hh1);
        uint2 lo = make_uint2(*(uint32_t*)&ll0, *(uint32_t*)&ll1);
        ((uint2*)g_khi)[i] = ho; ((uint2*)g_klo)[i] = lo;
    }
}

// ---------------------------------------------------------------------------
// Kernel 1: 3xFP16 GEMM via mma.sync (m16n8k16), 128x128 tile, 512 threads,
// double-buffered cp.async, fused per-32col softmax partials in epilogue.
// ---------------------------------------------------------------------------
static constexpr int S_AHI = 0;
static constexpr int S_ALO = 16384;
static constexpr int S_BHI = 32768;
static constexpr int S_BLO = 49152;
static constexpr int STAGE = 65536;
static constexpr int GEMM_SMEM = 2 * STAGE;   // 128 KB

__global__ __launch_bounds__(512) void gemm_tc_kernel(float* __restrict__ S)
{
    extern __shared__ char smem[];
    const uint32_t sbase = smem_u32(smem);
    const int tid = threadIdx.x;
    const int wid  = tid >> 5;
    const int lane = tid & 31;
    const int g  = lane >> 2;     // groupID 0..7
    const int tg = lane & 3;      // thread-in-group 0..3
    const int wm = (wid >> 2) * 32;   // warp m base in tile
    const int wn = (wid & 3)  * 32;   // warp n base in tile

    const int b  = blockIdx.z;
    const int m0 = blockIdx.y * TM;
    const int n0 = blockIdx.x * TN;

    const uint4* qhi4 = (const uint4*)(g_qhi + (size_t)b * N_ * D_);
    const uint4* qlo4 = (const uint4*)(g_qlo + (size_t)b * N_ * D_);
    const uint4* khi4 = (const uint4*)(g_khi + (size_t)b * N_ * D_);
    const uint4* klo4 = (const uint4*)(g_klo + (size_t)b * N_ * D_);

    const int l_row0 = tid >> 3;
    const int l_c4   = tid & 7;
    const int l_row1 = (tid + 512) >> 3;
    const uint32_t l_sw0 = (uint32_t)(l_row0 * 128 + (l_c4 * 16 ^ ((l_row0 & 7) << 4)));
    const uint32_t l_sw1 = (uint32_t)(l_row1 * 128 + (l_c4 * 16 ^ ((l_row1 & 7) << 4)));

    auto load_stage = [&](int c, int buf) {
        const uint32_t sb = sbase + buf * STAGE;
        const int k4 = c * 8;
        size_t gA0 = (size_t)(m0 + l_row0) * 32 + k4 + l_c4;
        size_t gA1 = (size_t)(m0 + l_row1) * 32 + k4 + l_c4;
        size_t gB0 = (size_t)(n0 + l_row0) * 32 + k4 + l_c4;
        size_t gB1 = (size_t)(n0 + l_row1) * 32 + k4 + l_c4;
        cpasync16(sb + S_AHI + l_sw0, qhi4 + gA0);
        cpasync16(sb + S_AHI + l_sw1, qhi4 + gA1);
        cpasync16(sb + S_ALO + l_sw0, qlo4 + gA0);
        cpasync16(sb + S_ALO + l_sw1, qlo4 + gA1);
        cpasync16(sb + S_BHI + l_sw0, khi4 + gB0);
        cpasync16(sb + S_BHI + l_sw1, khi4 + gB1);
        cpasync16(sb + S_BLO + l_sw0, klo4 + gB0);
        cpasync16(sb + S_BLO + l_sw1, klo4 + gB1);
    };

    int ra[2][2], rb[4];
#pragma unroll
    for (int t = 0; t < 2; t++) {
        ra[t][0] = (wm + t * 16 + g) * 128;
        ra[t][1] = (wm + t * 16 + g + 8) * 128;
    }
#pragma unroll
    for (int u = 0; u < 4; u++) rb[u] = (wn + u * 8 + g) * 128;
    const int gx = g << 4;

    float acc[2][4][4];
#pragma unroll
    for (int t = 0; t < 2; t++)
#pragma unroll
        for (int u = 0; u < 4; u++)
#pragma unroll
            for (int r = 0; r < 4; r++) acc[t][u][r] = 0.0f;

    load_stage(0, 0);
    CP_COMMIT();

    for (int c = 0; c < NCHUNKS; c++) {
        if (c + 1 < NCHUNKS) { load_stage(c + 1, (c + 1) & 1); CP_COMMIT(); CP_WAIT(1); }
        else                 { CP_WAIT(0); }
        __syncthreads();

        const char* sb = smem + (c & 1) * STAGE;
#pragma unroll
        for (int ks = 0; ks < 4; ks++) {
            const int kb  = ks * 32 + tg * 4;
            const int kx0 = kb ^ gx;
            const int kx1 = (kb + 16) ^ gx;

            uint32_t ahi[2][4], alo[2][4], bhi[4][2], blo[4][2];
#pragma unroll
            for (int t = 0; t < 2; t++) {
                ahi[t][0] = *(const uint32_t*)(sb + S_AHI + ra[t][0] + kx0);
                ahi[t][1] = *(const uint32_t*)(sb + S_AHI + ra[t][1] + kx0);
                ahi[t][2] = *(const uint32_t*)(sb + S_AHI + ra[t][0] + kx1);
                ahi[t][3] = *(const uint32_t*)(sb + S_AHI + ra[t][1] + kx1);
                alo[t][0] = *(const uint32_t*)(sb + S_ALO + ra[t][0] + kx0);
                alo[t][1] = *(const uint32_t*)(sb + S_ALO + ra[t][1] + kx0);
                alo[t][2] = *(const uint32_t*)(sb + S_ALO + ra[t][0] + kx1);
                alo[t][3] = *(const uint32_t*)(sb + S_ALO + ra[t][1] + kx1);
            }
#pragma unroll
            for (int u = 0; u < 4; u++) {
                bhi[u][0] = *(const uint32_t*)(sb + S_BHI + rb[u] + kx0);
                bhi[u][1] = *(const uint32_t*)(sb + S_BHI + rb[u] + kx1);
                blo[u][0] = *(const uint32_t*)(sb + S_BLO + rb[u] + kx0);
                blo[u][1] = *(const uint32_t*)(sb + S_BLO + rb[u] + kx1);
            }
#pragma unroll
            for (int t = 0; t < 2; t++)
#pragma unroll
                for (int u = 0; u < 4; u++) {
                    mma_f16(acc[t][u], ahi[t], bhi[u]);
                    mma_f16(acc[t][u], ahi[t], blo[u]);
                    mma_f16(acc[t][u], alo[t], bhi[u]);
                }
        }
        __syncthreads();
    }

    const int seg = (n0 >> 5) + (wid & 3);
#pragma unroll
    for (int t = 0; t < 2; t++) {
#pragma unroll
        for (int h = 0; h < 2; h++) {
            const int row = m0 + wm + t * 16 + g + h * 8;
            float* Sr = S + ((size_t)b * N_ + row) * N_ + n0 + wn;
            float mx = -INFINITY;
#pragma unroll
            for (int u = 0; u < 4; u++) {
                float v0 = acc[t][u][h * 2], v1 = acc[t][u][h * 2 + 1];
                *(float2*)(Sr + u * 8 + tg * 2) = make_float2(v0, v1);
                mx = fmaxf(mx, fmaxf(v0, v1));
            }
            mx = fmaxf(mx, __shfl_xor_sync(0xffffffffu, mx, 1));
            mx = fmaxf(mx, __shfl_xor_sync(0xffffffffu, mx, 2));
            float sm = 0.0f;
#pragma unroll
            for (int u = 0; u < 4; u++)
                sm += expf(acc[t][u][h * 2] - mx) + expf(acc[t][u][h * 2 + 1] - mx);
            sm += __shfl_xor_sync(0xffffffffu, sm, 1);
            sm += __shfl_xor_sync(0xffffffffu, sm, 2);
            if (tg == 0)
                g_part[((size_t)b * N_ + row) * NSEG + seg] = make_float2(mx, sm);
        }
    }
}

// ---------------------------------------------------------------------------
// Kernel 2: combine per-seg partials -> diagonal softmax prob per row
// ---------------------------------------------------------------------------
__global__ __launch_bounds__(256) void combine_kernel(const float* __restrict__ S)
{
    const int row  = blockIdx.x * 8 + (threadIdx.x >> 5);
    const int lane = threadIdx.x & 31;
    const float2* p = g_part + (size_t)row * NSEG;
    float2 p0 = p[lane], p1 = p[lane + 32];
    float m = fmaxf(p0.x, p1.x);
#pragma unroll
    for (int o = 16; o > 0; o >>= 1) m = fmaxf(m, __shfl_xor_sync(0xffffffffu, m, o));
    float Z = p0.y * expf(p0.x - m) + p1.y * expf(p1.x - m);
#pragma unroll
    for (int o = 16; o > 0; o >>= 1) Z += __shfl_xor_sync(0xffffffffu, Z, o);
    if (lane == 0) {
        const int i = row & (N_ - 1);
        g_diag[row] = expf(S[(size_t)row * N_ + i] - m) / Z;
    }
}

// ---------------------------------------------------------------------------
// Kernel 3a: rank counting — selected iff rank < K (exact same predicate as
// descending sort with ascending-index tiebreak).  8 blocks per batch.
// ---------------------------------------------------------------------------
__global__ __launch_bounds__(256) void rank_kernel()
{
    __shared__ float d[N_];
    const int b   = blockIdx.x >> 3;
    const int seg = blockIdx.x & 7;
    const float* src = g_diag + b * N_;
    for (int i = threadIdx.x; i < N_; i += 256) d[i] = src[i];
    __syncthreads();

    const int i = seg * 256 + threadIdx.x;
    const float di = d[i];
    int rank = 0;
#pragma unroll 8
    for (int j = 0; j < N_; j++) {
        float dj = d[j];
        rank += (dj > di) || (dj == di && j < i);
    }
    g_flag[b * N_ + i] = (rank < K_) ? 1 : 0;
}

// ---------------------------------------------------------------------------
// Kernel 3b: stable compaction of flags -> g_inst (ascending indices).
// One block of 1024 threads per batch; each thread owns elements 2t, 2t+1.
// ---------------------------------------------------------------------------
__global__ __launch_bounds__(1024) void compact_kernel()
{
    __shared__ int s[1024];
    const int b = blockIdx.x;
    const int t = threadIdx.x;
    const int f0 = g_flag[b * N_ + 2 * t];
    const int f1 = g_flag[b * N_ + 2 * t + 1];
    const int mysum = f0 + f1;
    s[t] = mysum;
    __syncthreads();
    // Hillis-Steele inclusive scan
    for (int off = 1; off < 1024; off <<= 1) {
        int val = (t >= off) ? s[t - off] : 0;
        __syncthreads();
        s[t] += val;
        __syncthreads();
    }
    const int excl = s[t] - mysum;
    if (f0) g_inst[b * K_ + excl] = 2 * t;
    if (f1) g_inst[b * K_ + excl + f0] = 2 * t + 1;
}

// ---------------------------------------------------------------------------
// Kernel 4: warp-level top-32 selection per (b,a) with gather prefetch.
// ---------------------------------------------------------------------------
__device__ __forceinline__ bool kv_before(float va, int ia, float vb, int ib) {
    return (va > vb) || (va == vb && ia < ib);
}

__global__ __launch_bounds__(256) void select_kernel(
    const float* __restrict__ S, float* __restrict__ out)
{
    const int warp = threadIdx.x >> 5;
    const int lane = threadIdx.x & 31;
    const int b = blockIdx.x >> 6;
    const int a = ((blockIdx.x & 63) << 3) + warp;

    __shared__ int s_inst[K_];
    for (int c = threadIdx.x; c < K_; c += 256) s_inst[c] = g_inst[b * K_ + c];
    __syncthreads();

    const int ia = s_inst[a];
    const float* Srow = S + ((size_t)b * N_ + ia) * N_;

    float v; int idx;
    float nxt = Srow[s_inst[32 + lane]];   // prefetch chunk 1

    {
        int c = lane;
        float x = Srow[s_inst[c]];
        if (c == a) x = __int_as_float(0x7f800000);
        v = x; idx = c;
#pragma unroll
        for (int k = 2; k <= 32; k <<= 1) {
#pragma unroll
            for (int j = k >> 1; j > 0; j >>= 1) {
                float pv = __shfl_xor_sync(0xffffffffu, v, j);
                int   pi = __shfl_xor_sync(0xffffffffu, idx, j);
                bool desc  = ((lane & k) == 0);
                bool lower = ((lane & j) == 0);
                bool win = kv_before(v, idx, pv, pi);
                bool take = (desc == lower) ? !win : win;
                if (take) { v = pv; idx = pi; }
            }
        }
    }

#pragma unroll
    for (int t = 1; t < 16; t++) {
        float v2 = nxt;
        if (t < 15) nxt = Srow[s_inst[(t + 1) * 32 + lane]];   // prefetch t+1
        int c = t * 32 + lane;
        if (c == a) v2 = __int_as_float(0x7f800000);
        int i2 = c;
#pragma unroll
        for (int k = 2; k <= 32; k <<= 1) {
#pragma unroll
            for (int j = k >> 1; j > 0; j >>= 1) {
                float pv = __shfl_xor_sync(0xffffffffu, v2, j);
                int   pi = __shfl_xor_sync(0xffffffffu, i2, j);
                bool desc  = ((lane & k) == 0);
                bool lower = ((lane & j) == 0);
                bool win = kv_before(v2, i2, pv, pi);
                bool take = (desc == lower) ? !win : win;
                if (take) { v2 = pv; i2 = pi; }
            }
        }
        float cv = __shfl_xor_sync(0xffffffffu, v2, 31);
        int   ci = __shfl_xor_sync(0xffffffffu, i2, 31);
        if (!kv_before(v, idx, cv, ci)) { v = cv; idx = ci; }
#pragma unroll
        for (int j = 16; j > 0; j >>= 1) {
            float pv = __shfl_xor_sync(0xffffffffu, v, j);
            int   pi = __shfl_xor_sync(0xffffffffu, idx, j);
            bool lower = ((lane & j) == 0);
            bool win = kv_before(v, idx, pv, pi);
            bool take = lower ? !win : win;
            if (take) { v = pv; idx = pi; }
        }
    }

#pragma unroll
    for (int k = 2; k <= 32; k <<= 1) {
#pragma unroll
        for (int j = k >> 1; j > 0; j >>= 1) {
            int pi = __shfl_xor_sync(0xffffffffu, idx, j);
            bool asc   = ((lane & k) == 0);
            bool lower = ((lane & j) == 0);
            bool win = (idx < pi);
            bool take = (asc == lower) ? !win : win;
            if (take) idx = pi;
        }
    }

    const int obj = s_inst[idx];
    const size_t base = (size_t)b * K_ + a;
    g_obj[base * R_ + lane] = obj;
    float* soi = out + SOI_OFF + base * R_ * 3 + lane * 3;
    soi[0] = (float)b;
    soi[1] = (float)ia;
    soi[2] = (float)obj;
}

// ---------------------------------------------------------------------------
// Kernel 5: emit rel_e. One block per (b,a); 8 warps x 4 relations each;
// subject row loaded once per warp (L1-resident across warps).
// ---------------------------------------------------------------------------
__global__ __launch_bounds__(256) void emit_kernel(
    const float* __restrict__ Q, float* __restrict__ out)
{
    const int blk  = blockIdx.x;
    const int b    = blk >> 9;
    const int a    = blk & (K_ - 1);
    const int wid  = threadIdx.x >> 5;
    const int lane = threadIdx.x & 31;

    const int ia = g_inst[b * K_ + a];
    const float4* qa4 = (const float4*)(Q + ((size_t)b * N_ + ia) * D_) + lane * 2;
    const float4 a0 = qa4[0], a1 = qa4[1];

    const size_t base = (size_t)b * K_ + a;

#pragma unroll
    for (int it = 0; it < 4; it++) {
        const int r = wid * 4 + it;
        const int obj = g_obj[base * R_ + r];
        const float4* qo = (const float4*)(Q + ((size_t)b * N_ + obj) * D_) + lane * 2;
        float4 x0 = qo[0], x1 = qo[1];
        x0.x += a0.x; x0.y += a0.y; x0.z += a0.z; x0.w += a0.w;
        x1.x += a1.x; x1.y += a1.y; x1.z += a1.z; x1.w += a1.w;

        float s = x0.x + x0.y + x0.z + x0.w + x1.x + x1.y + x1.z + x1.w;
#pragma unroll
        for (int o = 16; o > 0; o >>= 1) s += __shfl_xor_sync(0xffffffffu, s, o);
        const float mu = s * (1.0f / 256.0f);

        float d0x = x0.x - mu, d0y = x0.y - mu, d0z = x0.z - mu, d0w = x0.w - mu;
        float d1x = x1.x - mu, d1y = x1.y - mu, d1z = x1.z - mu, d1w = x1.w - mu;
        float s2 = d0x*d0x + d0y*d0y + d0z*d0z + d0w*d0w
                 + d1x*d1x + d1y*d1y + d1z*d1z + d1w*d1w;
#pragma unroll
        for (int o = 16; o > 0; o >>= 1) s2 += __shfl_xor_sync(0xffffffffu, s2, o);
        const float rn = rsqrtf(s2 * (1.0f / 256.0f) + 1e-5f);

        float4* o4 = (float4*)(out + RELE_OFF + (base * R_ + r) * D_) + lane * 2;
        o4[0] = make_float4(d0x * rn, d0y * rn, d0z * rn, d0w * rn);
        o4[1] = make_float4(d1x * rn, d1y * rn, d1z * rn, d1w * rn);
    }
}

// ---------------------------------------------------------------------------
extern "C" void kernel_launch(void* const* d_in, const int* in_sizes, int n_in,
                              void* d_out, int out_size)
{
    const float* q = (const float*)d_in[0];
    const float* k = (const float*)d_in[1];
    float* out = (float*)d_out;
    float* S = out;

    cudaFuncSetAttribute(gemm_tc_kernel,
                         cudaFuncAttributeMaxDynamicSharedMemorySize, GEMM_SMEM);

    decomp_kernel<<<(B_ * N_ * D_ / 4) / 256, 256>>>(q, k);

    dim3 gGemm(N_ / TN, N_ / TM, B_);
    gemm_tc_kernel<<<gGemm, 512, GEMM_SMEM>>>(S);

    combine_kernel<<<B_ * N_ / 8, 256>>>(S);

    rank_kernel<<<B_ * 8, 256>>>();
    compact_kernel<<<B_, 1024>>>();

    select_kernel<<<B_ * K_ / 8, 256>>>(S, out);

    emit_kernel<<<B_ * K_, 256>>>(q, out);
}

// round 7
// speedup vs baseline: 2.7223x; 1.0240x over previous
#include <cuda_runtime.h>
#include <cuda_fp16.h>
#include <math.h>
#include <stdint.h>

#define B_ 8
#define N_ 2048
#define D_ 256
#define K_ 512
#define R_ 32
#define NSEG 64      // N_ / 32 column segments for softmax partials

// GEMM tiling
#define TM 128
#define TN 128
#define BK 64
#define NCHUNKS (D_ / BK)   // 4

// Output packing: scores1 [B,N,N] | soi [B,K*R,3] | rel_e [B,K*R,D], all float32
static constexpr size_t SCORES_ELEMS = (size_t)B_ * N_ * N_;
static constexpr size_t SOI_OFF      = SCORES_ELEMS;
static constexpr size_t RELE_OFF     = SOI_OFF + (size_t)B_ * K_ * R_ * 3;

// Scratch (__device__ globals; no allocation allowed)
__device__ float2 g_part[(size_t)B_ * N_ * NSEG];
__device__ float  g_diag[B_ * N_];
__device__ int    g_flag[B_ * N_];
__device__ int    g_inst[B_ * K_];
__device__ int    g_obj [B_ * K_ * R_];
__device__ __half g_qhi[(size_t)B_ * N_ * D_];
__device__ __half g_qlo[(size_t)B_ * N_ * D_];
__device__ __half g_khi[(size_t)B_ * N_ * D_];
__device__ __half g_klo[(size_t)B_ * N_ * D_];

// ---------------------------------------------------------------------------
// helpers
// ---------------------------------------------------------------------------
__device__ __forceinline__ uint32_t smem_u32(const void* p) {
    uint32_t a;
    asm("{ .reg .u64 t; cvta.to.shared.u64 t, %1; cvt.u32.u64 %0, t; }" : "=r"(a) : "l"(p));
    return a;
}
__device__ __forceinline__ void cpasync16(uint32_t saddr, const void* g) {
    asm volatile("cp.async.ca.shared.global [%0], [%1], 16;" :: "r"(saddr), "l"(g) : "memory");
}
#define CP_COMMIT() asm volatile("cp.async.commit_group;" ::: "memory")
#define CP_WAIT(n)  asm volatile("cp.async.wait_group %0;" :: "n"(n) : "memory")

__device__ __forceinline__ void mma_f16(float* c, const uint32_t* a, const uint32_t* b) {
    asm volatile(
        "mma.sync.aligned.m16n8k16.row.col.f32.f16.f16.f32 "
        "{%0,%1,%2,%3}, {%4,%5,%6,%7}, {%8,%9}, {%0,%1,%2,%3};"
        : "+f"(c[0]), "+f"(c[1]), "+f"(c[2]), "+f"(c[3])
        : "r"(a[0]), "r"(a[1]), "r"(a[2]), "r"(a[3]), "r"(b[0]), "r"(b[1]));
}

// ---------------------------------------------------------------------------
// Kernel 0: split fp32 -> (hi, lo) fp16 pair for q and k
// ---------------------------------------------------------------------------
__global__ __launch_bounds__(256) void decomp_kernel(
    const float* __restrict__ q, const float* __restrict__ k)
{
    const size_t i = (size_t)blockIdx.x * 256 + threadIdx.x;  // float4 index
    {
        float4 x = ((const float4*)q)[i];
        __half h0 = __float2half_rn(x.x), h1 = __float2half_rn(x.y);
        __half h2 = __float2half_rn(x.z), h3 = __float2half_rn(x.w);
        __half l0 = __float2half_rn(x.x - __half2float(h0));
        __half l1 = __float2half_rn(x.y - __half2float(h1));
        __half l2 = __float2half_rn(x.z - __half2float(h2));
        __half l3 = __float2half_rn(x.w - __half2float(h3));
        __half2 hh0 = __halves2half2(h0, h1), hh1 = __halves2half2(h2, h3);
        __half2 ll0 = __halves2half2(l0, l1), ll1 = __halves2half2(l2, l3);
        uint2 ho = make_uint2(*(uint32_t*)&hh0, *(uint32_t*)&hh1);
        uint2 lo = make_uint2(*(uint32_t*)&ll0, *(uint32_t*)&ll1);
        ((uint2*)g_qhi)[i] = ho; ((uint2*)g_qlo)[i] = lo;
    }
    {
        float4 x = ((const float4*)k)[i];
        __half h0 = __float2half_rn(x.x), h1 = __float2half_rn(x.y);
        __half h2 = __float2half_rn(x.z), h3 = __float2half_rn(x.w);
        __half l0 = __float2half_rn(x.x - __half2float(h0));
        __half l1 = __float2half_rn(x.y - __half2float(h1));
        __half l2 = __float2half_rn(x.z - __half2float(h2));
        __half l3 = __float2half_rn(x.w - __half2float(h3));
        __half2 hh0 = __halves2half2(h0, h1), hh1 = __halves2half2(h2, h3);
        __half2 ll0 = __halves2half2(l0, l1), ll1 = __halves2half2(l2, l3);
        uint2 ho = make_uint2(*(uint32_t*)&hh0, *(uint32_t*)&hh1);
        uint2 lo = make_uint2(*(uint32_t*)&ll0, *(uint32_t*)&ll1);
        ((uint2*)g_khi)[i] = ho; ((uint2*)g_klo)[i] = lo;
    }
}

// ---------------------------------------------------------------------------
// Kernel 1: 3xFP16 GEMM via mma.sync (m16n8k16), 128x128 tile, 512 threads,
// double-buffered cp.async, fused per-32col softmax partials in epilogue.
// ---------------------------------------------------------------------------
static constexpr int S_AHI = 0;
static constexpr int S_ALO = 16384;
static constexpr int S_BHI = 32768;
static constexpr int S_BLO = 49152;
static constexpr int STAGE = 65536;
static constexpr int GEMM_SMEM = 2 * STAGE;   // 128 KB

__global__ __launch_bounds__(512) void gemm_tc_kernel(float* __restrict__ S)
{
    extern __shared__ char smem[];
    const uint32_t sbase = smem_u32(smem);
    const int tid = threadIdx.x;
    const int wid  = tid >> 5;
    const int lane = tid & 31;
    const int g  = lane >> 2;     // groupID 0..7
    const int tg = lane & 3;      // thread-in-group 0..3
    const int wm = (wid >> 2) * 32;   // warp m base in tile
    const int wn = (wid & 3)  * 32;   // warp n base in tile

    const int b  = blockIdx.z;
    const int m0 = blockIdx.y * TM;
    const int n0 = blockIdx.x * TN;

    const uint4* qhi4 = (const uint4*)(g_qhi + (size_t)b * N_ * D_);
    const uint4* qlo4 = (const uint4*)(g_qlo + (size_t)b * N_ * D_);
    const uint4* khi4 = (const uint4*)(g_khi + (size_t)b * N_ * D_);
    const uint4* klo4 = (const uint4*)(g_klo + (size_t)b * N_ * D_);

    const int l_row0 = tid >> 3;
    const int l_c4   = tid & 7;
    const int l_row1 = (tid + 512) >> 3;
    const uint32_t l_sw0 = (uint32_t)(l_row0 * 128 + (l_c4 * 16 ^ ((l_row0 & 7) << 4)));
    const uint32_t l_sw1 = (uint32_t)(l_row1 * 128 + (l_c4 * 16 ^ ((l_row1 & 7) << 4)));

    auto load_stage = [&](int c, int buf) {
        const uint32_t sb = sbase + buf * STAGE;
        const int k4 = c * 8;
        size_t gA0 = (size_t)(m0 + l_row0) * 32 + k4 + l_c4;
        size_t gA1 = (size_t)(m0 + l_row1) * 32 + k4 + l_c4;
        size_t gB0 = (size_t)(n0 + l_row0) * 32 + k4 + l_c4;
        size_t gB1 = (size_t)(n0 + l_row1) * 32 + k4 + l_c4;
        cpasync16(sb + S_AHI + l_sw0, qhi4 + gA0);
        cpasync16(sb + S_AHI + l_sw1, qhi4 + gA1);
        cpasync16(sb + S_ALO + l_sw0, qlo4 + gA0);
        cpasync16(sb + S_ALO + l_sw1, qlo4 + gA1);
        cpasync16(sb + S_BHI + l_sw0, khi4 + gB0);
        cpasync16(sb + S_BHI + l_sw1, khi4 + gB1);
        cpasync16(sb + S_BLO + l_sw0, klo4 + gB0);
        cpasync16(sb + S_BLO + l_sw1, klo4 + gB1);
    };

    int ra[2][2], rb[4];
#pragma unroll
    for (int t = 0; t < 2; t++) {
        ra[t][0] = (wm + t * 16 + g) * 128;
        ra[t][1] = (wm + t * 16 + g + 8) * 128;
    }
#pragma unroll
    for (int u = 0; u < 4; u++) rb[u] = (wn + u * 8 + g) * 128;
    const int gx = g << 4;

    float acc[2][4][4];
#pragma unroll
    for (int t = 0; t < 2; t++)
#pragma unroll
        for (int u = 0; u < 4; u++)
#pragma unroll
            for (int r = 0; r < 4; r++) acc[t][u][r] = 0.0f;

    load_stage(0, 0);
    CP_COMMIT();

    for (int c = 0; c < NCHUNKS; c++) {
        if (c + 1 < NCHUNKS) { load_stage(c + 1, (c + 1) & 1); CP_COMMIT(); CP_WAIT(1); }
        else                 { CP_WAIT(0); }
        __syncthreads();

        const char* sb = smem + (c & 1) * STAGE;
#pragma unroll
        for (int ks = 0; ks < 4; ks++) {
            const int kb  = ks * 32 + tg * 4;
            const int kx0 = kb ^ gx;
            const int kx1 = (kb + 16) ^ gx;

            uint32_t ahi[2][4], alo[2][4], bhi[4][2], blo[4][2];
#pragma unroll
            for (int t = 0; t < 2; t++) {
                ahi[t][0] = *(const uint32_t*)(sb + S_AHI + ra[t][0] + kx0);
                ahi[t][1] = *(const uint32_t*)(sb + S_AHI + ra[t][1] + kx0);
                ahi[t][2] = *(const uint32_t*)(sb + S_AHI + ra[t][0] + kx1);
                ahi[t][3] = *(const uint32_t*)(sb + S_AHI + ra[t][1] + kx1);
                alo[t][0] = *(const uint32_t*)(sb + S_ALO + ra[t][0] + kx0);
                alo[t][1] = *(const uint32_t*)(sb + S_ALO + ra[t][1] + kx0);
                alo[t][2] = *(const uint32_t*)(sb + S_ALO + ra[t][0] + kx1);
                alo[t][3] = *(const uint32_t*)(sb + S_ALO + ra[t][1] + kx1);
            }
#pragma unroll
            for (int u = 0; u < 4; u++) {
                bhi[u][0] = *(const uint32_t*)(sb + S_BHI + rb[u] + kx0);
                bhi[u][1] = *(const uint32_t*)(sb + S_BHI + rb[u] + kx1);
                blo[u][0] = *(const uint32_t*)(sb + S_BLO + rb[u] + kx0);
                blo[u][1] = *(const uint32_t*)(sb + S_BLO + rb[u] + kx1);
            }
#pragma unroll
            for (int t = 0; t < 2; t++)
#pragma unroll
                for (int u = 0; u < 4; u++) {
                    mma_f16(acc[t][u], ahi[t], bhi[u]);
                    mma_f16(acc[t][u], ahi[t], blo[u]);
                    mma_f16(acc[t][u], alo[t], bhi[u]);
                }
        }
        __syncthreads();
    }

    const int seg = (n0 >> 5) + (wid & 3);
#pragma unroll
    for (int t = 0; t < 2; t++) {
#pragma unroll
        for (int h = 0; h < 2; h++) {
            const int row = m0 + wm + t * 16 + g + h * 8;
            float* Sr = S + ((size_t)b * N_ + row) * N_ + n0 + wn;
            float mx = -INFINITY;
#pragma unroll
            for (int u = 0; u < 4; u++) {
                float v0 = acc[t][u][h * 2], v1 = acc[t][u][h * 2 + 1];
                *(float2*)(Sr + u * 8 + tg * 2) = make_float2(v0, v1);
                mx = fmaxf(mx, fmaxf(v0, v1));
            }
            mx = fmaxf(mx, __shfl_xor_sync(0xffffffffu, mx, 1));
            mx = fmaxf(mx, __shfl_xor_sync(0xffffffffu, mx, 2));
            float sm = 0.0f;
#pragma unroll
            for (int u = 0; u < 4; u++)
                sm += expf(acc[t][u][h * 2] - mx) + expf(acc[t][u][h * 2 + 1] - mx);
            sm += __shfl_xor_sync(0xffffffffu, sm, 1);
            sm += __shfl_xor_sync(0xffffffffu, sm, 2);
            if (tg == 0)
                g_part[((size_t)b * N_ + row) * NSEG + seg] = make_float2(mx, sm);
        }
    }
}

// ---------------------------------------------------------------------------
// Kernel 2: combine per-seg partials -> diagonal softmax prob per row
// ---------------------------------------------------------------------------
__global__ __launch_bounds__(256) void combine_kernel(const float* __restrict__ S)
{
    const int row  = blockIdx.x * 8 + (threadIdx.x >> 5);
    const int lane = threadIdx.x & 31;
    const float2* p = g_part + (size_t)row * NSEG;
    float2 p0 = p[lane], p1 = p[lane + 32];
    float m = fmaxf(p0.x, p1.x);
#pragma unroll
    for (int o = 16; o > 0; o >>= 1) m = fmaxf(m, __shfl_xor_sync(0xffffffffu, m, o));
    float Z = p0.y * expf(p0.x - m) + p1.y * expf(p1.x - m);
#pragma unroll
    for (int o = 16; o > 0; o >>= 1) Z += __shfl_xor_sync(0xffffffffu, Z, o);
    if (lane == 0) {
        const int i = row & (N_ - 1);
        g_diag[row] = expf(S[(size_t)row * N_ + i] - m) / Z;
    }
}

// ---------------------------------------------------------------------------
// Kernel 3a: rank counting, one WARP per element i. Lane sums over
// j = lane + 32*t; shfl reduce. Same selection predicate as before.
// Grid: B*N/8 blocks, 8 warps each.
// ---------------------------------------------------------------------------
__global__ __launch_bounds__(256) void rank_kernel()
{
    __shared__ float d[N_];
    const int i_base = blockIdx.x * 8;            // 8 elements per block
    const int b = i_base >> 11;                   // / N_
    const int wid  = threadIdx.x >> 5;
    const int lane = threadIdx.x & 31;

    const float* src = g_diag + b * N_;
    for (int i = threadIdx.x; i < N_; i += 256) d[i] = src[i];
    __syncthreads();

    const int i = (i_base & (N_ - 1)) + wid;      // element within batch
    const float di = d[i];
    int rank = 0;
#pragma unroll
    for (int t = 0; t < N_ / 32; t++) {
        const int j = t * 32 + lane;
        const float dj = d[j];
        rank += (dj > di) || (dj == di && j < i);
    }
#pragma unroll
    for (int o = 16; o > 0; o >>= 1) rank += __shfl_xor_sync(0xffffffffu, rank, o);
    if (lane == 0) g_flag[b * N_ + i] = (rank < K_) ? 1 : 0;
}

// ---------------------------------------------------------------------------
// Kernel 3b: stable compaction of flags -> g_inst (ascending indices).
// ---------------------------------------------------------------------------
__global__ __launch_bounds__(1024) void compact_kernel()
{
    __shared__ int s[1024];
    const int b = blockIdx.x;
    const int t = threadIdx.x;
    const int f0 = g_flag[b * N_ + 2 * t];
    const int f1 = g_flag[b * N_ + 2 * t + 1];
    const int mysum = f0 + f1;
    s[t] = mysum;
    __syncthreads();
    for (int off = 1; off < 1024; off <<= 1) {
        int val = (t >= off) ? s[t - off] : 0;
        __syncthreads();
        s[t] += val;
        __syncthreads();
    }
    const int excl = s[t] - mysum;
    if (f0) g_inst[b * K_ + excl] = 2 * t;
    if (f1) g_inst[b * K_ + excl + f0] = 2 * t + 1;
}

// ---------------------------------------------------------------------------
// Kernel 4: warp-level top-32 selection per (b,a) with gather prefetch.
// ---------------------------------------------------------------------------
__device__ __forceinline__ bool kv_before(float va, int ia, float vb, int ib) {
    return (va > vb) || (va == vb && ia < ib);
}

__global__ __launch_bounds__(256) void select_kernel(
    const float* __restrict__ S, float* __restrict__ out)
{
    const int warp = threadIdx.x >> 5;
    const int lane = threadIdx.x & 31;
    const int b = blockIdx.x >> 6;
    const int a = ((blockIdx.x & 63) << 3) + warp;

    __shared__ int s_inst[K_];
    for (int c = threadIdx.x; c < K_; c += 256) s_inst[c] = g_inst[b * K_ + c];
    __syncthreads();

    const int ia = s_inst[a];
    const float* Srow = S + ((size_t)b * N_ + ia) * N_;

    float v; int idx;
    float nxt = Srow[s_inst[32 + lane]];   // prefetch chunk 1

    {
        int c = lane;
        float x = Srow[s_inst[c]];
        if (c == a) x = __int_as_float(0x7f800000);
        v = x; idx = c;
#pragma unroll
        for (int k = 2; k <= 32; k <<= 1) {
#pragma unroll
            for (int j = k >> 1; j > 0; j >>= 1) {
                float pv = __shfl_xor_sync(0xffffffffu, v, j);
                int   pi = __shfl_xor_sync(0xffffffffu, idx, j);
                bool desc  = ((lane & k) == 0);
                bool lower = ((lane & j) == 0);
                bool win = kv_before(v, idx, pv, pi);
                bool take = (desc == lower) ? !win : win;
                if (take) { v = pv; idx = pi; }
            }
        }
    }

#pragma unroll
    for (int t = 1; t < 16; t++) {
        float v2 = nxt;
        if (t < 15) nxt = Srow[s_inst[(t + 1) * 32 + lane]];   // prefetch t+1
        int c = t * 32 + lane;
        if (c == a) v2 = __int_as_float(0x7f800000);
        int i2 = c;
#pragma unroll
        for (int k = 2; k <= 32; k <<= 1) {
#pragma unroll
            for (int j = k >> 1; j > 0; j >>= 1) {
                float pv = __shfl_xor_sync(0xffffffffu, v2, j);
                int   pi = __shfl_xor_sync(0xffffffffu, i2, j);
                bool desc  = ((lane & k) == 0);
                bool lower = ((lane & j) == 0);
                bool win = kv_before(v2, i2, pv, pi);
                bool take = (desc == lower) ? !win : win;
                if (take) { v2 = pv; i2 = pi; }
            }
        }
        float cv = __shfl_xor_sync(0xffffffffu, v2, 31);
        int   ci = __shfl_xor_sync(0xffffffffu, i2, 31);
        if (!kv_before(v, idx, cv, ci)) { v = cv; idx = ci; }
#pragma unroll
        for (int j = 16; j > 0; j >>= 1) {
            float pv = __shfl_xor_sync(0xffffffffu, v, j);
            int   pi = __shfl_xor_sync(0xffffffffu, idx, j);
            bool lower = ((lane & j) == 0);
            bool win = kv_before(v, idx, pv, pi);
            bool take = lower ? !win : win;
            if (take) { v = pv; idx = pi; }
        }
    }

#pragma unroll
    for (int k = 2; k <= 32; k <<= 1) {
#pragma unroll
        for (int j = k >> 1; j > 0; j >>= 1) {
            int pi = __shfl_xor_sync(0xffffffffu, idx, j);
            bool asc   = ((lane & k) == 0);
            bool lower = ((lane & j) == 0);
            bool win = (idx < pi);
            bool take = (asc == lower) ? !win : win;
            if (take) idx = pi;
        }
    }

    const int obj = s_inst[idx];
    const size_t base = (size_t)b * K_ + a;
    g_obj[base * R_ + lane] = obj;
    float* soi = out + SOI_OFF + base * R_ * 3 + lane * 3;
    soi[0] = (float)b;
    soi[1] = (float)ia;
    soi[2] = (float)obj;
}

// ---------------------------------------------------------------------------
// Kernel 5: emit rel_e. One block per (b,a); 8 warps x 4 relations each.
// ---------------------------------------------------------------------------
__global__ __launch_bounds__(256) void emit_kernel(
    const float* __restrict__ Q, float* __restrict__ out)
{
    const int blk  = blockIdx.x;
    const int b    = blk >> 9;
    const int a    = blk & (K_ - 1);
    const int wid  = threadIdx.x >> 5;
    const int lane = threadIdx.x & 31;

    const int ia = g_inst[b * K_ + a];
    const float4* qa4 = (const float4*)(Q + ((size_t)b * N_ + ia) * D_) + lane * 2;
    const float4 a0 = qa4[0], a1 = qa4[1];

    const size_t base = (size_t)b * K_ + a;

#pragma unroll
    for (int it = 0; it < 4; it++) {
        const int r = wid * 4 + it;
        const int obj = g_obj[base * R_ + r];
        const float4* qo = (const float4*)(Q + ((size_t)b * N_ + obj) * D_) + lane * 2;
        float4 x0 = qo[0], x1 = qo[1];
        x0.x += a0.x; x0.y += a0.y; x0.z += a0.z; x0.w += a0.w;
        x1.x += a1.x; x1.y += a1.y; x1.z += a1.z; x1.w += a1.w;

        float s = x0.x + x0.y + x0.z + x0.w + x1.x + x1.y + x1.z + x1.w;
#pragma unroll
        for (int o = 16; o > 0; o >>= 1) s += __shfl_xor_sync(0xffffffffu, s, o);
        const float mu = s * (1.0f / 256.0f);

        float d0x = x0.x - mu, d0y = x0.y - mu, d0z = x0.z - mu, d0w = x0.w - mu;
        float d1x = x1.x - mu, d1y = x1.y - mu, d1z = x1.z - mu, d1w = x1.w - mu;
        float s2 = d0x*d0x + d0y*d0y + d0z*d0z + d0w*d0w
                 + d1x*d1x + d1y*d1y + d1z*d1z + d1w*d1w;
#pragma unroll
        for (int o = 16; o > 0; o >>= 1) s2 += __shfl_xor_sync(0xffffffffu, s2, o);
        const float rn = rsqrtf(s2 * (1.0f / 256.0f) + 1e-5f);

        float4* o4 = (float4*)(out + RELE_OFF + (base * R_ + r) * D_) + lane * 2;
        o4[0] = make_float4(d0x * rn, d0y * rn, d0z * rn, d0w * rn);
        o4[1] = make_float4(d1x * rn, d1y * rn, d1z * rn, d1w * rn);
    }
}

// ---------------------------------------------------------------------------
extern "C" void kernel_launch(void* const* d_in, const int* in_sizes, int n_in,
                              void* d_out, int out_size)
{
    const float* q = (const float*)d_in[0];
    const float* k = (const float*)d_in[1];
    float* out = (float*)d_out;
    float* S = out;

    cudaFuncSetAttribute(gemm_tc_kernel,
                         cudaFuncAttributeMaxDynamicSharedMemorySize, GEMM_SMEM);

    decomp_kernel<<<(B_ * N_ * D_ / 4) / 256, 256>>>(q, k);

    dim3 gGemm(N_ / TN, N_ / TM, B_);
    gemm_tc_kernel<<<gGemm, 512, GEMM_SMEM>>>(S);

    combine_kernel<<<B_ * N_ / 8, 256>>>(S);

    rank_kernel<<<B_ * N_ / 8, 256>>>();
    compact_kernel<<<B_, 1024>>>();

    select_kernel<<<B_ * K_ / 8, 256>>>(S, out);

    emit_kernel<<<B_ * K_, 256>>>(q, out);
}

// round 8
// speedup vs baseline: 2.7605x; 1.0140x over previous
#include <cuda_runtime.h>
#include <cuda_fp16.h>
#include <math.h>
#include <stdint.h>

#define B_ 8
#define N_ 2048
#define D_ 256
#define K_ 512
#define R_ 32
#define NSEG 64      // N_ / 32 column segments for softmax partials

// GEMM tiling
#define TM 128
#define TN 128
#define BK 64
#define NCHUNKS (D_ / BK)   // 4

// Output packing: scores1 [B,N,N] | soi [B,K*R,3] | rel_e [B,K*R,D], all float32
static constexpr size_t SCORES_ELEMS = (size_t)B_ * N_ * N_;
static constexpr size_t SOI_OFF      = SCORES_ELEMS;
static constexpr size_t RELE_OFF     = SOI_OFF + (size_t)B_ * K_ * R_ * 3;

// Scratch (__device__ globals; no allocation allowed)
__device__ float2 g_part[(size_t)B_ * N_ * NSEG];
__device__ float  g_diag[B_ * N_];
__device__ int    g_flag[B_ * N_];
__device__ int    g_inst[B_ * K_];
__device__ int    g_obj [B_ * K_ * R_];
__device__ __half g_qhi[(size_t)B_ * N_ * D_];
__device__ __half g_qlo[(size_t)B_ * N_ * D_];
__device__ __half g_khi[(size_t)B_ * N_ * D_];
__device__ __half g_klo[(size_t)B_ * N_ * D_];

// ---------------------------------------------------------------------------
// helpers
// ---------------------------------------------------------------------------
__device__ __forceinline__ uint32_t smem_u32(const void* p) {
    uint32_t a;
    asm("{ .reg .u64 t; cvta.to.shared.u64 t, %1; cvt.u32.u64 %0, t; }" : "=r"(a) : "l"(p));
    return a;
}
__device__ __forceinline__ void cpasync16(uint32_t saddr, const void* g) {
    asm volatile("cp.async.ca.shared.global [%0], [%1], 16;" :: "r"(saddr), "l"(g) : "memory");
}
#define CP_COMMIT() asm volatile("cp.async.commit_group;" ::: "memory")
#define CP_WAIT(n)  asm volatile("cp.async.wait_group %0;" :: "n"(n) : "memory")

__device__ __forceinline__ void mma_f16(float* c, const uint32_t* a, const uint32_t* b) {
    asm volatile(
        "mma.sync.aligned.m16n8k16.row.col.f32.f16.f16.f32 "
        "{%0,%1,%2,%3}, {%4,%5,%6,%7}, {%8,%9}, {%0,%1,%2,%3};"
        : "+f"(c[0]), "+f"(c[1]), "+f"(c[2]), "+f"(c[3])
        : "r"(a[0]), "r"(a[1]), "r"(a[2]), "r"(a[3]), "r"(b[0]), "r"(b[1]));
}

// ---------------------------------------------------------------------------
// Kernel 0: split fp32 -> (hi, lo) fp16 pair for q and k
// ---------------------------------------------------------------------------
__global__ __launch_bounds__(256) void decomp_kernel(
    const float* __restrict__ q, const float* __restrict__ k)
{
    const size_t i = (size_t)blockIdx.x * 256 + threadIdx.x;  // float4 index
    {
        float4 x = ((const float4*)q)[i];
        __half h0 = __float2half_rn(x.x), h1 = __float2half_rn(x.y);
        __half h2 = __float2half_rn(x.z), h3 = __float2half_rn(x.w);
        __half l0 = __float2half_rn(x.x - __half2float(h0));
        __half l1 = __float2half_rn(x.y - __half2float(h1));
        __half l2 = __float2half_rn(x.z - __half2float(h2));
        __half l3 = __float2half_rn(x.w - __half2float(h3));
        __half2 hh0 = __halves2half2(h0, h1), hh1 = __halves2half2(h2, h3);
        __half2 ll0 = __halves2half2(l0, l1), ll1 = __halves2half2(l2, l3);
        uint2 ho = make_uint2(*(uint32_t*)&hh0, *(uint32_t*)&hh1);
        uint2 lo = make_uint2(*(uint32_t*)&ll0, *(uint32_t*)&ll1);
        ((uint2*)g_qhi)[i] = ho; ((uint2*)g_qlo)[i] = lo;
    }
    {
        float4 x = ((const float4*)k)[i];
        __half h0 = __float2half_rn(x.x), h1 = __float2half_rn(x.y);
        __half h2 = __float2half_rn(x.z), h3 = __float2half_rn(x.w);
        __half l0 = __float2half_rn(x.x - __half2float(h0));
        __half l1 = __float2half_rn(x.y - __half2float(h1));
        __half l2 = __float2half_rn(x.z - __half2float(h2));
        __half l3 = __float2half_rn(x.w - __half2float(h3));
        __half2 hh0 = __halves2half2(h0, h1), hh1 = __halves2half2(h2, h3);
        __half2 ll0 = __halves2half2(l0, l1), ll1 = __halves2half2(l2, l3);
        uint2 ho = make_uint2(*(uint32_t*)&hh0, *(uint32_t*)&hh1);
        uint2 lo = make_uint2(*(uint32_t*)&ll0, *(uint32_t*)&ll1);
        ((uint2*)g_khi)[i] = ho; ((uint2*)g_klo)[i] = lo;
    }
}

// ---------------------------------------------------------------------------
// Kernel 1: 3xFP16 GEMM via mma.sync (m16n8k16), 128x128 tile, 512 threads,
// double-buffered cp.async + register-double-buffered fragments,
// pass-outer MMA ordering (RAW distance 8), fused softmax partials.
// ---------------------------------------------------------------------------
static constexpr int S_AHI = 0;
static constexpr int S_ALO = 16384;
static constexpr int S_BHI = 32768;
static constexpr int S_BLO = 49152;
static constexpr int STAGE = 65536;
static constexpr int GEMM_SMEM = 2 * STAGE;   // 128 KB

__global__ __launch_bounds__(512) void gemm_tc_kernel(float* __restrict__ S)
{
    extern __shared__ char smem[];
    const uint32_t sbase = smem_u32(smem);
    const int tid = threadIdx.x;
    const int wid  = tid >> 5;
    const int lane = tid & 31;
    const int g  = lane >> 2;     // groupID 0..7
    const int tg = lane & 3;      // thread-in-group 0..3
    const int wm = (wid >> 2) * 32;   // warp m base in tile
    const int wn = (wid & 3)  * 32;   // warp n base in tile

    const int b  = blockIdx.z;
    const int m0 = blockIdx.y * TM;
    const int n0 = blockIdx.x * TN;

    const uint4* qhi4 = (const uint4*)(g_qhi + (size_t)b * N_ * D_);
    const uint4* qlo4 = (const uint4*)(g_qlo + (size_t)b * N_ * D_);
    const uint4* khi4 = (const uint4*)(g_khi + (size_t)b * N_ * D_);
    const uint4* klo4 = (const uint4*)(g_klo + (size_t)b * N_ * D_);

    const int l_row0 = tid >> 3;
    const int l_c4   = tid & 7;
    const int l_row1 = (tid + 512) >> 3;
    const uint32_t l_sw0 = (uint32_t)(l_row0 * 128 + (l_c4 * 16 ^ ((l_row0 & 7) << 4)));
    const uint32_t l_sw1 = (uint32_t)(l_row1 * 128 + (l_c4 * 16 ^ ((l_row1 & 7) << 4)));

    auto load_stage = [&](int c, int buf) {
        const uint32_t sb = sbase + buf * STAGE;
        const int k4 = c * 8;
        size_t gA0 = (size_t)(m0 + l_row0) * 32 + k4 + l_c4;
        size_t gA1 = (size_t)(m0 + l_row1) * 32 + k4 + l_c4;
        size_t gB0 = (size_t)(n0 + l_row0) * 32 + k4 + l_c4;
        size_t gB1 = (size_t)(n0 + l_row1) * 32 + k4 + l_c4;
        cpasync16(sb + S_AHI + l_sw0, qhi4 + gA0);
        cpasync16(sb + S_AHI + l_sw1, qhi4 + gA1);
        cpasync16(sb + S_ALO + l_sw0, qlo4 + gA0);
        cpasync16(sb + S_ALO + l_sw1, qlo4 + gA1);
        cpasync16(sb + S_BHI + l_sw0, khi4 + gB0);
        cpasync16(sb + S_BHI + l_sw1, khi4 + gB1);
        cpasync16(sb + S_BLO + l_sw0, klo4 + gB0);
        cpasync16(sb + S_BLO + l_sw1, klo4 + gB1);
    };

    int ra[2][2], rb[4];
#pragma unroll
    for (int t = 0; t < 2; t++) {
        ra[t][0] = (wm + t * 16 + g) * 128;
        ra[t][1] = (wm + t * 16 + g + 8) * 128;
    }
#pragma unroll
    for (int u = 0; u < 4; u++) rb[u] = (wn + u * 8 + g) * 128;
    const int gx = g << 4;

    // fragment register double buffer
    uint32_t ahi[2][2][4], alo[2][2][4], bhi[2][4][2], blo[2][4][2];

    auto load_frags = [&](const char* sb, int ks, int rbuf) {
        const int kb  = ks * 32 + tg * 4;
        const int kx0 = kb ^ gx;
        const int kx1 = (kb + 16) ^ gx;
#pragma unroll
        for (int t = 0; t < 2; t++) {
            ahi[rbuf][t][0] = *(const uint32_t*)(sb + S_AHI + ra[t][0] + kx0);
            ahi[rbuf][t][1] = *(const uint32_t*)(sb + S_AHI + ra[t][1] + kx0);
            ahi[rbuf][t][2] = *(const uint32_t*)(sb + S_AHI + ra[t][0] + kx1);
            ahi[rbuf][t][3] = *(const uint32_t*)(sb + S_AHI + ra[t][1] + kx1);
            alo[rbuf][t][0] = *(const uint32_t*)(sb + S_ALO + ra[t][0] + kx0);
            alo[rbuf][t][1] = *(const uint32_t*)(sb + S_ALO + ra[t][1] + kx0);
            alo[rbuf][t][2] = *(const uint32_t*)(sb + S_ALO + ra[t][0] + kx1);
            alo[rbuf][t][3] = *(const uint32_t*)(sb + S_ALO + ra[t][1] + kx1);
        }
#pragma unroll
        for (int u = 0; u < 4; u++) {
            bhi[rbuf][u][0] = *(const uint32_t*)(sb + S_BHI + rb[u] + kx0);
            bhi[rbuf][u][1] = *(const uint32_t*)(sb + S_BHI + rb[u] + kx1);
            blo[rbuf][u][0] = *(const uint32_t*)(sb + S_BLO + rb[u] + kx0);
            blo[rbuf][u][1] = *(const uint32_t*)(sb + S_BLO + rb[u] + kx1);
        }
    };

    float acc[2][4][4];
#pragma unroll
    for (int t = 0; t < 2; t++)
#pragma unroll
        for (int u = 0; u < 4; u++)
#pragma unroll
            for (int r = 0; r < 4; r++) acc[t][u][r] = 0.0f;

    load_stage(0, 0);
    CP_COMMIT();

    for (int c = 0; c < NCHUNKS; c++) {
        if (c + 1 < NCHUNKS) { load_stage(c + 1, (c + 1) & 1); CP_COMMIT(); CP_WAIT(1); }
        else                 { CP_WAIT(0); }
        __syncthreads();

        const char* sb = smem + (c & 1) * STAGE;
        load_frags(sb, 0, 0);
#pragma unroll
        for (int ks = 0; ks < 4; ks++) {
            const int cur = ks & 1;
            if (ks < 3) load_frags(sb, ks + 1, cur ^ 1);
            // pass-outer ordering: RAW distance 8 on each accumulator
#pragma unroll
            for (int t = 0; t < 2; t++)
#pragma unroll
                for (int u = 0; u < 4; u++)
                    mma_f16(acc[t][u], ahi[cur][t], bhi[cur][u]);
#pragma unroll
            for (int t = 0; t < 2; t++)
#pragma unroll
                for (int u = 0; u < 4; u++)
                    mma_f16(acc[t][u], ahi[cur][t], blo[cur][u]);
#pragma unroll
            for (int t = 0; t < 2; t++)
#pragma unroll
                for (int u = 0; u < 4; u++)
                    mma_f16(acc[t][u], alo[cur][t], bhi[cur][u]);
        }
        __syncthreads();
    }

    const int seg = (n0 >> 5) + (wid & 3);
#pragma unroll
    for (int t = 0; t < 2; t++) {
#pragma unroll
        for (int h = 0; h < 2; h++) {
            const int row = m0 + wm + t * 16 + g + h * 8;
            float* Sr = S + ((size_t)b * N_ + row) * N_ + n0 + wn;
            float mx = -INFINITY;
#pragma unroll
            for (int u = 0; u < 4; u++) {
                float v0 = acc[t][u][h * 2], v1 = acc[t][u][h * 2 + 1];
                *(float2*)(Sr + u * 8 + tg * 2) = make_float2(v0, v1);
                mx = fmaxf(mx, fmaxf(v0, v1));
            }
            mx = fmaxf(mx, __shfl_xor_sync(0xffffffffu, mx, 1));
            mx = fmaxf(mx, __shfl_xor_sync(0xffffffffu, mx, 2));
            float sm = 0.0f;
#pragma unroll
            for (int u = 0; u < 4; u++)
                sm += expf(acc[t][u][h * 2] - mx) + expf(acc[t][u][h * 2 + 1] - mx);
            sm += __shfl_xor_sync(0xffffffffu, sm, 1);
            sm += __shfl_xor_sync(0xffffffffu, sm, 2);
            if (tg == 0)
                g_part[((size_t)b * N_ + row) * NSEG + seg] = make_float2(mx, sm);
        }
    }
}

// ---------------------------------------------------------------------------
// Kernel 2: combine per-seg partials -> diagonal softmax prob per row
// ---------------------------------------------------------------------------
__global__ __launch_bounds__(256) void combine_kernel(const float* __restrict__ S)
{
    const int row  = blockIdx.x * 8 + (threadIdx.x >> 5);
    const int lane = threadIdx.x & 31;
    const float2* p = g_part + (size_t)row * NSEG;
    float2 p0 = p[lane], p1 = p[lane + 32];
    float m = fmaxf(p0.x, p1.x);
#pragma unroll
    for (int o = 16; o > 0; o >>= 1) m = fmaxf(m, __shfl_xor_sync(0xffffffffu, m, o));
    float Z = p0.y * expf(p0.x - m) + p1.y * expf(p1.x - m);
#pragma unroll
    for (int o = 16; o > 0; o >>= 1) Z += __shfl_xor_sync(0xffffffffu, Z, o);
    if (lane == 0) {
        const int i = row & (N_ - 1);
        g_diag[row] = expf(S[(size_t)row * N_ + i] - m) / Z;
    }
}

// ---------------------------------------------------------------------------
// Kernel 3a: rank counting with 64-bit monotone keys.
// diag > 0 -> float bits order-isomorphic. key = (bits<<32)|(N-1-i):
// key_j > key_i  <=>  (dj > di) || (dj==di && j<i).  One warp per element.
// ---------------------------------------------------------------------------
__global__ __launch_bounds__(256) void rank_kernel()
{
    __shared__ unsigned long long kk[N_];
    const int i_base = blockIdx.x * 8;
    const int b = i_base >> 11;
    const int wid  = threadIdx.x >> 5;
    const int lane = threadIdx.x & 31;

    const float* src = g_diag + b * N_;
    for (int i = threadIdx.x; i < N_; i += 256) {
        unsigned long long bits = (unsigned long long)__float_as_uint(src[i]);
        kk[i] = (bits << 32) | (unsigned)(N_ - 1 - i);
    }
    __syncthreads();

    const int i = (i_base & (N_ - 1)) + wid;
    const unsigned long long ki = kk[i];
    int rank = 0;
#pragma unroll
    for (int t = 0; t < N_ / 32; t++)
        rank += (kk[t * 32 + lane] > ki);
#pragma unroll
    for (int o = 16; o > 0; o >>= 1) rank += __shfl_xor_sync(0xffffffffu, rank, o);
    if (lane == 0) g_flag[b * N_ + i] = (rank < K_) ? 1 : 0;
}

// ---------------------------------------------------------------------------
// Kernel 3b: stable compaction of flags -> g_inst (ascending indices).
// ---------------------------------------------------------------------------
__global__ __launch_bounds__(1024) void compact_kernel()
{
    __shared__ int s[1024];
    const int b = blockIdx.x;
    const int t = threadIdx.x;
    const int f0 = g_flag[b * N_ + 2 * t];
    const int f1 = g_flag[b * N_ + 2 * t + 1];
    const int mysum = f0 + f1;
    s[t] = mysum;
    __syncthreads();
    for (int off = 1; off < 1024; off <<= 1) {
        int val = (t >= off) ? s[t - off] : 0;
        __syncthreads();
        s[t] += val;
        __syncthreads();
    }
    const int excl = s[t] - mysum;
    if (f0) g_inst[b * K_ + excl] = 2 * t;
    if (f1) g_inst[b * K_ + excl + f0] = 2 * t + 1;
}

// ---------------------------------------------------------------------------
// Kernel 4: warp-level top-32 selection per (b,a) with gather prefetch.
// ---------------------------------------------------------------------------
__device__ __forceinline__ bool kv_before(float va, int ia, float vb, int ib) {
    return (va > vb) || (va == vb && ia < ib);
}

__global__ __launch_bounds__(256) void select_kernel(
    const float* __restrict__ S, float* __restrict__ out)
{
    const int warp = threadIdx.x >> 5;
    const int lane = threadIdx.x & 31;
    const int b = blockIdx.x >> 6;
    const int a = ((blockIdx.x & 63) << 3) + warp;

    __shared__ int s_inst[K_];
    for (int c = threadIdx.x; c < K_; c += 256) s_inst[c] = g_inst[b * K_ + c];
    __syncthreads();

    const int ia = s_inst[a];
    const float* Srow = S + ((size_t)b * N_ + ia) * N_;

    float v; int idx;
    float nxt = Srow[s_inst[32 + lane]];

    {
        int c = lane;
        float x = Srow[s_inst[c]];
        if (c == a) x = __int_as_float(0x7f800000);
        v = x; idx = c;
#pragma unroll
        for (int k = 2; k <= 32; k <<= 1) {
#pragma unroll
            for (int j = k >> 1; j > 0; j >>= 1) {
                float pv = __shfl_xor_sync(0xffffffffu, v, j);
                int   pi = __shfl_xor_sync(0xffffffffu, idx, j);
                bool desc  = ((lane & k) == 0);
                bool lower = ((lane & j) == 0);
                bool win = kv_before(v, idx, pv, pi);
                bool take = (desc == lower) ? !win : win;
                if (take) { v = pv; idx = pi; }
            }
        }
    }

#pragma unroll
    for (int t = 1; t < 16; t++) {
        float v2 = nxt;
        if (t < 15) nxt = Srow[s_inst[(t + 1) * 32 + lane]];
        int c = t * 32 + lane;
        if (c == a) v2 = __int_as_float(0x7f800000);
        int i2 = c;
#pragma unroll
        for (int k = 2; k <= 32; k <<= 1) {
#pragma unroll
            for (int j = k >> 1; j > 0; j >>= 1) {
                float pv = __shfl_xor_sync(0xffffffffu, v2, j);
                int   pi = __shfl_xor_sync(0xffffffffu, i2, j);
                bool desc  = ((lane & k) == 0);
                bool lower = ((lane & j) == 0);
                bool win = kv_before(v2, i2, pv, pi);
                bool take = (desc == lower) ? !win : win;
                if (take) { v2 = pv; i2 = pi; }
            }
        }
        float cv = __shfl_xor_sync(0xffffffffu, v2, 31);
        int   ci = __shfl_xor_sync(0xffffffffu, i2, 31);
        if (!kv_before(v, idx, cv, ci)) { v = cv; idx = ci; }
#pragma unroll
        for (int j = 16; j > 0; j >>= 1) {
            float pv = __shfl_xor_sync(0xffffffffu, v, j);
            int   pi = __shfl_xor_sync(0xffffffffu, idx, j);
            bool lower = ((lane & j) == 0);
            bool win = kv_before(v, idx, pv, pi);
            bool take = lower ? !win : win;
            if (take) { v = pv; idx = pi; }
        }
    }

#pragma unroll
    for (int k = 2; k <= 32; k <<= 1) {
#pragma unroll
        for (int j = k >> 1; j > 0; j >>= 1) {
            int pi = __shfl_xor_sync(0xffffffffu, idx, j);
            bool asc   = ((lane & k) == 0);
            bool lower = ((lane & j) == 0);
            bool win = (idx < pi);
            bool take = (asc == lower) ? !win : win;
            if (take) idx = pi;
        }
    }

    const int obj = s_inst[idx];
    const size_t base = (size_t)b * K_ + a;
    g_obj[base * R_ + lane] = obj;
    float* soi = out + SOI_OFF + base * R_ * 3 + lane * 3;
    soi[0] = (float)b;
    soi[1] = (float)ia;
    soi[2] = (float)obj;
}

// ---------------------------------------------------------------------------
// Kernel 5: emit rel_e. One block per (b,a); 8 warps x 4 relations each.
// ---------------------------------------------------------------------------
__global__ __launch_bounds__(256) void emit_kernel(
    const float* __restrict__ Q, float* __restrict__ out)
{
    const int blk  = blockIdx.x;
    const int b    = blk >> 9;
    const int a    = blk & (K_ - 1);
    const int wid  = threadIdx.x >> 5;
    const int lane = threadIdx.x & 31;

    const int ia = g_inst[b * K_ + a];
    const float4* qa4 = (const float4*)(Q + ((size_t)b * N_ + ia) * D_) + lane * 2;
    const float4 a0 = qa4[0], a1 = qa4[1];

    const size_t base = (size_t)b * K_ + a;

#pragma unroll
    for (int it = 0; it < 4; it++) {
        const int r = wid * 4 + it;
        const int obj = g_obj[base * R_ + r];
        const float4* qo = (const float4*)(Q + ((size_t)b * N_ + obj) * D_) + lane * 2;
        float4 x0 = qo[0], x1 = qo[1];
        x0.x += a0.x; x0.y += a0.y; x0.z += a0.z; x0.w += a0.w;
        x1.x += a1.x; x1.y += a1.y; x1.z += a1.z; x1.w += a1.w;

        float s = x0.x + x0.y + x0.z + x0.w + x1.x + x1.y + x1.z + x1.w;
#pragma unroll
        for (int o = 16; o > 0; o >>= 1) s += __shfl_xor_sync(0xffffffffu, s, o);
        const float mu = s * (1.0f / 256.0f);

        float d0x = x0.x - mu, d0y = x0.y - mu, d0z = x0.z - mu, d0w = x0.w - mu;
        float d1x = x1.x - mu, d1y = x1.y - mu, d1z = x1.z - mu, d1w = x1.w - mu;
        float s2 = d0x*d0x + d0y*d0y + d0z*d0z + d0w*d0w
                 + d1x*d1x + d1y*d1y + d1z*d1z + d1w*d1w;
#pragma unroll
        for (int o = 16; o > 0; o >>= 1) s2 += __shfl_xor_sync(0xffffffffu, s2, o);
        const float rn = rsqrtf(s2 * (1.0f / 256.0f) + 1e-5f);

        float4* o4 = (float4*)(out + RELE_OFF + (base * R_ + r) * D_) + lane * 2;
        o4[0] = make_float4(d0x * rn, d0y * rn, d0z * rn, d0w * rn);
        o4[1] = make_float4(d1x * rn, d1y * rn, d1z * rn, d1w * rn);
    }
}

// ---------------------------------------------------------------------------
extern "C" void kernel_launch(void* const* d_in, const int* in_sizes, int n_in,
                              void* d_out, int out_size)
{
    const float* q = (const float*)d_in[0];
    const float* k = (const float*)d_in[1];
    float* out = (float*)d_out;
    float* S = out;

    cudaFuncSetAttribute(gemm_tc_kernel,
                         cudaFuncAttributeMaxDynamicSharedMemorySize, GEMM_SMEM);

    decomp_kernel<<<(B_ * N_ * D_ / 4) / 256, 256>>>(q, k);

    dim3 gGemm(N_ / TN, N_ / TM, B_);
    gemm_tc_kernel<<<gGemm, 512, GEMM_SMEM>>>(S);

    combine_kernel<<<B_ * N_ / 8, 256>>>(S);

    rank_kernel<<<B_ * N_ / 8, 256>>>();
    compact_kernel<<<B_, 1024>>>();

    select_kernel<<<B_ * K_ / 8, 256>>>(S, out);

    emit_kernel<<<B_ * K_, 256>>>(q, out);
}

// round 9
// speedup vs baseline: 2.7870x; 1.0096x over previous
#include <cuda_runtime.h>
#include <cuda_fp16.h>
#include <math.h>
#include <stdint.h>

#define B_ 8
#define N_ 2048
#define D_ 256
#define K_ 512
#define R_ 32
#define NSEG 64      // N_ / 32 column segments for softmax partials

// GEMM tiling
#define TM 128
#define TN 128
#define BK 64
#define NCHUNKS (D_ / BK)   // 4

// Output packing: scores1 [B,N,N] | soi [B,K*R,3] | rel_e [B,K*R,D], all float32
static constexpr size_t SCORES_ELEMS = (size_t)B_ * N_ * N_;
static constexpr size_t SOI_OFF      = SCORES_ELEMS;
static constexpr size_t RELE_OFF     = SOI_OFF + (size_t)B_ * K_ * R_ * 3;

// Scratch (__device__ globals; no allocation allowed)
__device__ float2 g_part[(size_t)B_ * N_ * NSEG];
__device__ float  g_diag[B_ * N_];
__device__ int    g_inst[B_ * K_];
__device__ int    g_obj [B_ * K_ * R_];
__device__ __half g_qhi[(size_t)B_ * N_ * D_];
__device__ __half g_qlo[(size_t)B_ * N_ * D_];
__device__ __half g_khi[(size_t)B_ * N_ * D_];
__device__ __half g_klo[(size_t)B_ * N_ * D_];

// ---------------------------------------------------------------------------
// helpers
// ---------------------------------------------------------------------------
__device__ __forceinline__ uint32_t smem_u32(const void* p) {
    uint32_t a;
    asm("{ .reg .u64 t; cvta.to.shared.u64 t, %1; cvt.u32.u64 %0, t; }" : "=r"(a) : "l"(p));
    return a;
}
__device__ __forceinline__ void cpasync16(uint32_t saddr, const void* g) {
    asm volatile("cp.async.ca.shared.global [%0], [%1], 16;" :: "r"(saddr), "l"(g) : "memory");
}
#define CP_COMMIT() asm volatile("cp.async.commit_group;" ::: "memory")
#define CP_WAIT(n)  asm volatile("cp.async.wait_group %0;" :: "n"(n) : "memory")

__device__ __forceinline__ void mma_f16(float* c, const uint32_t* a, const uint32_t* b) {
    asm volatile(
        "mma.sync.aligned.m16n8k16.row.col.f32.f16.f16.f32 "
        "{%0,%1,%2,%3}, {%4,%5,%6,%7}, {%8,%9}, {%0,%1,%2,%3};"
        : "+f"(c[0]), "+f"(c[1]), "+f"(c[2]), "+f"(c[3])
        : "r"(a[0]), "r"(a[1]), "r"(a[2]), "r"(a[3]), "r"(b[0]), "r"(b[1]));
}

// ---------------------------------------------------------------------------
// Kernel 0: split fp32 -> (hi, lo) fp16 pair for q and k
// ---------------------------------------------------------------------------
__global__ __launch_bounds__(256) void decomp_kernel(
    const float* __restrict__ q, const float* __restrict__ k)
{
    const size_t i = (size_t)blockIdx.x * 256 + threadIdx.x;  // float4 index
    {
        float4 x = ((const float4*)q)[i];
        __half h0 = __float2half_rn(x.x), h1 = __float2half_rn(x.y);
        __half h2 = __float2half_rn(x.z), h3 = __float2half_rn(x.w);
        __half l0 = __float2half_rn(x.x - __half2float(h0));
        __half l1 = __float2half_rn(x.y - __half2float(h1));
        __half l2 = __float2half_rn(x.z - __half2float(h2));
        __half l3 = __float2half_rn(x.w - __half2float(h3));
        __half2 hh0 = __halves2half2(h0, h1), hh1 = __halves2half2(h2, h3);
        __half2 ll0 = __halves2half2(l0, l1), ll1 = __halves2half2(l2, l3);
        uint2 ho = make_uint2(*(uint32_t*)&hh0, *(uint32_t*)&hh1);
        uint2 lo = make_uint2(*(uint32_t*)&ll0, *(uint32_t*)&ll1);
        ((uint2*)g_qhi)[i] = ho; ((uint2*)g_qlo)[i] = lo;
    }
    {
        float4 x = ((const float4*)k)[i];
        __half h0 = __float2half_rn(x.x), h1 = __float2half_rn(x.y);
        __half h2 = __float2half_rn(x.z), h3 = __float2half_rn(x.w);
        __half l0 = __float2half_rn(x.x - __half2float(h0));
        __half l1 = __float2half_rn(x.y - __half2float(h1));
        __half l2 = __float2half_rn(x.z - __half2float(h2));
        __half l3 = __float2half_rn(x.w - __half2float(h3));
        __half2 hh0 = __halves2half2(h0, h1), hh1 = __halves2half2(h2, h3);
        __half2 ll0 = __halves2half2(l0, l1), ll1 = __halves2half2(l2, l3);
        uint2 ho = make_uint2(*(uint32_t*)&hh0, *(uint32_t*)&hh1);
        uint2 lo = make_uint2(*(uint32_t*)&ll0, *(uint32_t*)&ll1);
        ((uint2*)g_khi)[i] = ho; ((uint2*)g_klo)[i] = lo;
    }
}

// ---------------------------------------------------------------------------
// Kernel 1: 3xFP16 GEMM via mma.sync (m16n8k16), 128x128 tile, 512 threads,
// double-buffered cp.async + register-double-buffered fragments,
// pass-outer MMA ordering, fused softmax partials.
// ---------------------------------------------------------------------------
static constexpr int S_AHI = 0;
static constexpr int S_ALO = 16384;
static constexpr int S_BHI = 32768;
static constexpr int S_BLO = 49152;
static constexpr int STAGE = 65536;
static constexpr int GEMM_SMEM = 2 * STAGE;   // 128 KB

__global__ __launch_bounds__(512) void gemm_tc_kernel(float* __restrict__ S)
{
    extern __shared__ char smem[];
    const uint32_t sbase = smem_u32(smem);
    const int tid = threadIdx.x;
    const int wid  = tid >> 5;
    const int lane = tid & 31;
    const int g  = lane >> 2;     // groupID 0..7
    const int tg = lane & 3;      // thread-in-group 0..3
    const int wm = (wid >> 2) * 32;   // warp m base in tile
    const int wn = (wid & 3)  * 32;   // warp n base in tile

    const int b  = blockIdx.z;
    const int m0 = blockIdx.y * TM;
    const int n0 = blockIdx.x * TN;

    const uint4* qhi4 = (const uint4*)(g_qhi + (size_t)b * N_ * D_);
    const uint4* qlo4 = (const uint4*)(g_qlo + (size_t)b * N_ * D_);
    const uint4* khi4 = (const uint4*)(g_khi + (size_t)b * N_ * D_);
    const uint4* klo4 = (const uint4*)(g_klo + (size_t)b * N_ * D_);

    const int l_row0 = tid >> 3;
    const int l_c4   = tid & 7;
    const int l_row1 = (tid + 512) >> 3;
    const uint32_t l_sw0 = (uint32_t)(l_row0 * 128 + (l_c4 * 16 ^ ((l_row0 & 7) << 4)));
    const uint32_t l_sw1 = (uint32_t)(l_row1 * 128 + (l_c4 * 16 ^ ((l_row1 & 7) << 4)));

    auto load_stage = [&](int c, int buf) {
        const uint32_t sb = sbase + buf * STAGE;
        const int k4 = c * 8;
        size_t gA0 = (size_t)(m0 + l_row0) * 32 + k4 + l_c4;
        size_t gA1 = (size_t)(m0 + l_row1) * 32 + k4 + l_c4;
        size_t gB0 = (size_t)(n0 + l_row0) * 32 + k4 + l_c4;
        size_t gB1 = (size_t)(n0 + l_row1) * 32 + k4 + l_c4;
        cpasync16(sb + S_AHI + l_sw0, qhi4 + gA0);
        cpasync16(sb + S_AHI + l_sw1, qhi4 + gA1);
        cpasync16(sb + S_ALO + l_sw0, qlo4 + gA0);
        cpasync16(sb + S_ALO + l_sw1, qlo4 + gA1);
        cpasync16(sb + S_BHI + l_sw0, khi4 + gB0);
        cpasync16(sb + S_BHI + l_sw1, khi4 + gB1);
        cpasync16(sb + S_BLO + l_sw0, klo4 + gB0);
        cpasync16(sb + S_BLO + l_sw1, klo4 + gB1);
    };

    int ra[2][2], rb[4];
#pragma unroll
    for (int t = 0; t < 2; t++) {
        ra[t][0] = (wm + t * 16 + g) * 128;
        ra[t][1] = (wm + t * 16 + g + 8) * 128;
    }
#pragma unroll
    for (int u = 0; u < 4; u++) rb[u] = (wn + u * 8 + g) * 128;
    const int gx = g << 4;

    uint32_t ahi[2][2][4], alo[2][2][4], bhi[2][4][2], blo[2][4][2];

    auto load_frags = [&](const char* sb, int ks, int rbuf) {
        const int kb  = ks * 32 + tg * 4;
        const int kx0 = kb ^ gx;
        const int kx1 = (kb + 16) ^ gx;
#pragma unroll
        for (int t = 0; t < 2; t++) {
            ahi[rbuf][t][0] = *(const uint32_t*)(sb + S_AHI + ra[t][0] + kx0);
            ahi[rbuf][t][1] = *(const uint32_t*)(sb + S_AHI + ra[t][1] + kx0);
            ahi[rbuf][t][2] = *(const uint32_t*)(sb + S_AHI + ra[t][0] + kx1);
            ahi[rbuf][t][3] = *(const uint32_t*)(sb + S_AHI + ra[t][1] + kx1);
            alo[rbuf][t][0] = *(const uint32_t*)(sb + S_ALO + ra[t][0] + kx0);
            alo[rbuf][t][1] = *(const uint32_t*)(sb + S_ALO + ra[t][1] + kx0);
            alo[rbuf][t][2] = *(const uint32_t*)(sb + S_ALO + ra[t][0] + kx1);
            alo[rbuf][t][3] = *(const uint32_t*)(sb + S_ALO + ra[t][1] + kx1);
        }
#pragma unroll
        for (int u = 0; u < 4; u++) {
            bhi[rbuf][u][0] = *(const uint32_t*)(sb + S_BHI + rb[u] + kx0);
            bhi[rbuf][u][1] = *(const uint32_t*)(sb + S_BHI + rb[u] + kx1);
            blo[rbuf][u][0] = *(const uint32_t*)(sb + S_BLO + rb[u] + kx0);
            blo[rbuf][u][1] = *(const uint32_t*)(sb + S_BLO + rb[u] + kx1);
        }
    };

    float acc[2][4][4];
#pragma unroll
    for (int t = 0; t < 2; t++)
#pragma unroll
        for (int u = 0; u < 4; u++)
#pragma unroll
            for (int r = 0; r < 4; r++) acc[t][u][r] = 0.0f;

    load_stage(0, 0);
    CP_COMMIT();

    for (int c = 0; c < NCHUNKS; c++) {
        if (c + 1 < NCHUNKS) { load_stage(c + 1, (c + 1) & 1); CP_COMMIT(); CP_WAIT(1); }
        else                 { CP_WAIT(0); }
        __syncthreads();

        const char* sb = smem + (c & 1) * STAGE;
        load_frags(sb, 0, 0);
#pragma unroll
        for (int ks = 0; ks < 4; ks++) {
            const int cur = ks & 1;
            if (ks < 3) load_frags(sb, ks + 1, cur ^ 1);
#pragma unroll
            for (int t = 0; t < 2; t++)
#pragma unroll
                for (int u = 0; u < 4; u++)
                    mma_f16(acc[t][u], ahi[cur][t], bhi[cur][u]);
#pragma unroll
            for (int t = 0; t < 2; t++)
#pragma unroll
                for (int u = 0; u < 4; u++)
                    mma_f16(acc[t][u], ahi[cur][t], blo[cur][u]);
#pragma unroll
            for (int t = 0; t < 2; t++)
#pragma unroll
                for (int u = 0; u < 4; u++)
                    mma_f16(acc[t][u], alo[cur][t], bhi[cur][u]);
        }
        __syncthreads();
    }

    const int seg = (n0 >> 5) + (wid & 3);
#pragma unroll
    for (int t = 0; t < 2; t++) {
#pragma unroll
        for (int h = 0; h < 2; h++) {
            const int row = m0 + wm + t * 16 + g + h * 8;
            float* Sr = S + ((size_t)b * N_ + row) * N_ + n0 + wn;
            float mx = -INFINITY;
#pragma unroll
            for (int u = 0; u < 4; u++) {
                float v0 = acc[t][u][h * 2], v1 = acc[t][u][h * 2 + 1];
                *(float2*)(Sr + u * 8 + tg * 2) = make_float2(v0, v1);
                mx = fmaxf(mx, fmaxf(v0, v1));
            }
            mx = fmaxf(mx, __shfl_xor_sync(0xffffffffu, mx, 1));
            mx = fmaxf(mx, __shfl_xor_sync(0xffffffffu, mx, 2));
            float sm = 0.0f;
#pragma unroll
            for (int u = 0; u < 4; u++)
                sm += expf(acc[t][u][h * 2] - mx) + expf(acc[t][u][h * 2 + 1] - mx);
            sm += __shfl_xor_sync(0xffffffffu, sm, 1);
            sm += __shfl_xor_sync(0xffffffffu, sm, 2);
            if (tg == 0)
                g_part[((size_t)b * N_ + row) * NSEG + seg] = make_float2(mx, sm);
        }
    }
}

// ---------------------------------------------------------------------------
// Kernel 2: combine per-seg partials -> diagonal softmax prob per row
// ---------------------------------------------------------------------------
__global__ __launch_bounds__(256) void combine_kernel(const float* __restrict__ S)
{
    const int row  = blockIdx.x * 8 + (threadIdx.x >> 5);
    const int lane = threadIdx.x & 31;
    const float2* p = g_part + (size_t)row * NSEG;
    float2 p0 = p[lane], p1 = p[lane + 32];
    float m = fmaxf(p0.x, p1.x);
#pragma unroll
    for (int o = 16; o > 0; o >>= 1) m = fmaxf(m, __shfl_xor_sync(0xffffffffu, m, o));
    float Z = p0.y * expf(p0.x - m) + p1.y * expf(p1.x - m);
#pragma unroll
    for (int o = 16; o > 0; o >>= 1) Z += __shfl_xor_sync(0xffffffffu, Z, o);
    if (lane == 0) {
        const int i = row & (N_ - 1);
        g_diag[row] = expf(S[(size_t)row * N_ + i] - m) / Z;
    }
}

// ---------------------------------------------------------------------------
// Kernel 3: fused top-512 via binary-search threshold + stable compaction.
// One block (1024 threads) per batch. diag > 0 -> float bits order-isomorphic.
// Selection set = {bits > T} plus first need_eq lowest-index {bits == T},
// identical to rank-based predicate (desc value, asc index tiebreak).
// ---------------------------------------------------------------------------
__global__ __launch_bounds__(1024) void topk_kernel()
{
    __shared__ uint32_t bits[N_];
    __shared__ int red[32];
    __shared__ int s_cnt;
    __shared__ int scan[1024];

    const int b = blockIdx.x;
    const int t = threadIdx.x;
    const int wid = t >> 5, lane = t & 31;

    const float* src = g_diag + b * N_;
    bits[t]        = __float_as_uint(src[t]);
    bits[t + 1024] = __float_as_uint(src[t + 1024]);
    __syncthreads();

    const uint32_t b0 = bits[2 * t], b1 = bits[2 * t + 1];

    // binary search: T = smallest x with count(bits > x) < K
    uint32_t lo = 0, hi = 0x3F800000u;   // diag in (0, 1] -> bits <= bits(1.0f)
    while (lo < hi) {
        const uint32_t mid = lo + ((hi - lo) >> 1);
        int c = (b0 > mid) + (b1 > mid);
#pragma unroll
        for (int o = 16; o > 0; o >>= 1) c += __shfl_xor_sync(0xffffffffu, c, o);
        if (lane == 0) red[wid] = c;
        __syncthreads();
        if (t == 0) {
            int tot = 0;
#pragma unroll
            for (int w = 0; w < 32; w++) tot += red[w];
            s_cnt = tot;
        }
        __syncthreads();
        if (s_cnt >= K_) lo = mid + 1; else hi = mid;
    }
    const uint32_t T = lo;

    // packed scan: high 16 bits = count(bits > T), low 16 = count(bits == T)
    const int f0 = b0 > T,  f1 = b1 > T;
    const int e0 = b0 == T, e1 = b1 == T;
    scan[t] = ((f0 + f1) << 16) | (e0 + e1);
    __syncthreads();
    for (int off = 1; off < 1024; off <<= 1) {
        int v = (t >= off) ? scan[t - off] : 0;
        __syncthreads();
        scan[t] += v;
        __syncthreads();
    }
    const int incl = scan[t];
    const int total_gt = scan[1023] >> 16;
    const int need_eq = K_ - total_gt;
    const int excl_f = (incl >> 16) - (f0 + f1);
    const int excl_e = (incl & 0xFFFF) - (e0 + e1);

    const bool sel0 = f0 || (e0 && excl_e < need_eq);
    const bool sel1 = f1 || (e1 && (excl_e + e0) < need_eq);
    const int pos0 = excl_f + min(excl_e, need_eq);
    const int pos1 = excl_f + f0 + min(excl_e + e0, need_eq);
    if (sel0) g_inst[b * K_ + pos0] = 2 * t;
    if (sel1) g_inst[b * K_ + pos1] = 2 * t + 1;
}

// ---------------------------------------------------------------------------
// Kernel 4: warp-level top-32 selection per (b,a) with gather prefetch.
// ---------------------------------------------------------------------------
__device__ __forceinline__ bool kv_before(float va, int ia, float vb, int ib) {
    return (va > vb) || (va == vb && ia < ib);
}

__global__ __launch_bounds__(256) void select_kernel(
    const float* __restrict__ S, float* __restrict__ out)
{
    const int warp = threadIdx.x >> 5;
    const int lane = threadIdx.x & 31;
    const int b = blockIdx.x >> 6;
    const int a = ((blockIdx.x & 63) << 3) + warp;

    __shared__ int s_inst[K_];
    for (int c = threadIdx.x; c < K_; c += 256) s_inst[c] = g_inst[b * K_ + c];
    __syncthreads();

    const int ia = s_inst[a];
    const float* Srow = S + ((size_t)b * N_ + ia) * N_;

    float v; int idx;
    float nxt = Srow[s_inst[32 + lane]];

    {
        int c = lane;
        float x = Srow[s_inst[c]];
        if (c == a) x = __int_as_float(0x7f800000);
        v = x; idx = c;
#pragma unroll
        for (int k = 2; k <= 32; k <<= 1) {
#pragma unroll
            for (int j = k >> 1; j > 0; j >>= 1) {
                float pv = __shfl_xor_sync(0xffffffffu, v, j);
                int   pi = __shfl_xor_sync(0xffffffffu, idx, j);
                bool desc  = ((lane & k) == 0);
                bool lower = ((lane & j) == 0);
                bool win = kv_before(v, idx, pv, pi);
                bool take = (desc == lower) ? !win : win;
                if (take) { v = pv; idx = pi; }
            }
        }
    }

#pragma unroll
    for (int t = 1; t < 16; t++) {
        float v2 = nxt;
        if (t < 15) nxt = Srow[s_inst[(t + 1) * 32 + lane]];
        int c = t * 32 + lane;
        if (c == a) v2 = __int_as_float(0x7f800000);
        int i2 = c;
#pragma unroll
        for (int k = 2; k <= 32; k <<= 1) {
#pragma unroll
            for (int j = k >> 1; j > 0; j >>= 1) {
                float pv = __shfl_xor_sync(0xffffffffu, v2, j);
                int   pi = __shfl_xor_sync(0xffffffffu, i2, j);
                bool desc  = ((lane & k) == 0);
                bool lower = ((lane & j) == 0);
                bool win = kv_before(v2, i2, pv, pi);
                bool take = (desc == lower) ? !win : win;
                if (take) { v2 = pv; i2 = pi; }
            }
        }
        float cv = __shfl_xor_sync(0xffffffffu, v2, 31);
        int   ci = __shfl_xor_sync(0xffffffffu, i2, 31);
        if (!kv_before(v, idx, cv, ci)) { v = cv; idx = ci; }
#pragma unroll
        for (int j = 16; j > 0; j >>= 1) {
            float pv = __shfl_xor_sync(0xffffffffu, v, j);
            int   pi = __shfl_xor_sync(0xffffffffu, idx, j);
            bool lower = ((lane & j) == 0);
            bool win = kv_before(v, idx, pv, pi);
            bool take = lower ? !win : win;
            if (take) { v = pv; idx = pi; }
        }
    }

#pragma unroll
    for (int k = 2; k <= 32; k <<= 1) {
#pragma unroll
        for (int j = k >> 1; j > 0; j >>= 1) {
            int pi = __shfl_xor_sync(0xffffffffu, idx, j);
            bool asc   = ((lane & k) == 0);
            bool lower = ((lane & j) == 0);
            bool win = (idx < pi);
            bool take = (asc == lower) ? !win : win;
            if (take) idx = pi;
        }
    }

    const int obj = s_inst[idx];
    const size_t base = (size_t)b * K_ + a;
    g_obj[base * R_ + lane] = obj;
    float* soi = out + SOI_OFF + base * R_ * 3 + lane * 3;
    soi[0] = (float)b;
    soi[1] = (float)ia;
    soi[2] = (float)obj;
}

// ---------------------------------------------------------------------------
// Kernel 5: emit rel_e. One block per (b,a); 8 warps x 4 relations each.
// ---------------------------------------------------------------------------
__global__ __launch_bounds__(256) void emit_kernel(
    const float* __restrict__ Q, float* __restrict__ out)
{
    const int blk  = blockIdx.x;
    const int b    = blk >> 9;
    const int a    = blk & (K_ - 1);
    const int wid  = threadIdx.x >> 5;
    const int lane = threadIdx.x & 31;

    const int ia = g_inst[b * K_ + a];
    const float4* qa4 = (const float4*)(Q + ((size_t)b * N_ + ia) * D_) + lane * 2;
    const float4 a0 = qa4[0], a1 = qa4[1];

    const size_t base = (size_t)b * K_ + a;

#pragma unroll
    for (int it = 0; it < 4; it++) {
        const int r = wid * 4 + it;
        const int obj = g_obj[base * R_ + r];
        const float4* qo = (const float4*)(Q + ((size_t)b * N_ + obj) * D_) + lane * 2;
        float4 x0 = qo[0], x1 = qo[1];
        x0.x += a0.x; x0.y += a0.y; x0.z += a0.z; x0.w += a0.w;
        x1.x += a1.x; x1.y += a1.y; x1.z += a1.z; x1.w += a1.w;

        float s = x0.x + x0.y + x0.z + x0.w + x1.x + x1.y + x1.z + x1.w;
#pragma unroll
        for (int o = 16; o > 0; o >>= 1) s += __shfl_xor_sync(0xffffffffu, s, o);
        const float mu = s * (1.0f / 256.0f);

        float d0x = x0.x - mu, d0y = x0.y - mu, d0z = x0.z - mu, d0w = x0.w - mu;
        float d1x = x1.x - mu, d1y = x1.y - mu, d1z = x1.z - mu, d1w = x1.w - mu;
        float s2 = d0x*d0x + d0y*d0y + d0z*d0z + d0w*d0w
                 + d1x*d1x + d1y*d1y + d1z*d1z + d1w*d1w;
#pragma unroll
        for (int o = 16; o > 0; o >>= 1) s2 += __shfl_xor_sync(0xffffffffu, s2, o);
        const float rn = rsqrtf(s2 * (1.0f / 256.0f) + 1e-5f);

        float4* o4 = (float4*)(out + RELE_OFF + (base * R_ + r) * D_) + lane * 2;
        o4[0] = make_float4(d0x * rn, d0y * rn, d0z * rn, d0w * rn);
        o4[1] = make_float4(d1x * rn, d1y * rn, d1z * rn, d1w * rn);
    }
}

// ---------------------------------------------------------------------------
extern "C" void kernel_launch(void* const* d_in, const int* in_sizes, int n_in,
                              void* d_out, int out_size)
{
    const float* q = (const float*)d_in[0];
    const float* k = (const float*)d_in[1];
    float* out = (float*)d_out;
    float* S = out;

    cudaFuncSetAttribute(gemm_tc_kernel,
                         cudaFuncAttributeMaxDynamicSharedMemorySize, GEMM_SMEM);

    decomp_kernel<<<(B_ * N_ * D_ / 4) / 256, 256>>>(q, k);

    dim3 gGemm(N_ / TN, N_ / TM, B_);
    gemm_tc_kernel<<<gGemm, 512, GEMM_SMEM>>>(S);

    combine_kernel<<<B_ * N_ / 8, 256>>>(S);

    topk_kernel<<<B_, 1024>>>();

    select_kernel<<<B_ * K_ / 8, 256>>>(S, out);

    emit_kernel<<<B_ * K_, 256>>>(q, out);
}